// round 13
// baseline (speedup 1.0000x reference)
#include <cuda_runtime.h>
#include <cuda_bf16.h>
#include <math.h>
#include <cstdint>

#define BB   256
#define NPIX 1089
#define MDIM 272
#define CC   32

#define FLAG_ACT_IN 1
#define FLAG_FLIP   2
#define FLAG_ACTDER 4
#define FLAG_GNORM  8
#define FLAG_CONV1  16

// tensor-conv geometry
#define TC_THREADS 256
#define T1_THREADS 256
#define FRONT   40            /* zero rows before padded-pixel 0 */
#define SROWS   1360
#define ROWW    20            /* u32 per smem row (80B stride, conflict-free ldmatrix) */
#define NTILES  69            /* ceil(1089/16) pixel tiles */
#define KSTEPS  18            /* 9 taps * 32 ci / 16 */

#define OFF_ROWS 18560                           /* fragment-major weights: 36*512 = 18432 <= 18560 */
#define SMEM_TC  (OFF_ROWS + SROWS * ROWW * 4)   /* 127360 */
#define OFF_SZ   SMEM_TC
#define OFF_SW1  (OFF_SZ + SROWS * 4)            /* 132800 */
#define SMEM_TC2 (OFF_SW1 + 9 * CC * 4)          /* 133952 */
#define SMEM_T1N (SROWS * 64)                    /* 87040 */

// ---------------- device state (static, no allocation) ----------------
__device__ float d_P[NPIX*NPIX];
__device__ float d_PhiTb[BB*NPIX];
__device__ float d_x[BB*NPIX];
__device__ float d_z[BB*NPIX];
__device__ float d_gphi[BB*NPIX];
__device__ float d_dotm[BB*NPIX];
// pixel-major bf16 tensors: [image][pixel][32ch] as 16 u32 per pixel
__device__ unsigned int d_x1[BB*NPIX*16];
__device__ unsigned int d_x2[BB*NPIX*16];
__device__ unsigned int d_x3[BB*NPIX*16];
__device__ unsigned int d_g [BB*NPIX*16];
__device__ unsigned int d_bA[BB*NPIX*16];
__device__ float d_ngrad[BB];
__device__ float d_gamma;

__device__ __forceinline__ uint32_t smem_to_u32(const void* p) {
    uint32_t a;
    asm("{ .reg .u64 t; cvta.to.shared.u64 t, %1; cvt.u32.u64 %0, t; }" : "=r"(a) : "l"(p));
    return a;
}

// ---------------- bf16 pack/unpack ----------------
__device__ __forceinline__ float2 bupk(unsigned int u) {
    __nv_bfloat162 t = *reinterpret_cast<__nv_bfloat162*>(&u);
    return __bfloat1622float2(t);
}
__device__ __forceinline__ unsigned int bpk(float a, float b) {
    __nv_bfloat162 t = __floats2bfloat162_rn(a, b);
    return *reinterpret_cast<unsigned int*>(&t);
}

// ---------------- activation (eq. 33), DELTA = 0.01 ----------------
__device__ __forceinline__ float actf(float v) {
    if (fabsf(v) > 0.01f) return fmaxf(v, 0.0f);
    return fmaf(v*v, 25.0f, fmaf(v, 0.5f, 0.0025f));
}
__device__ __forceinline__ float actdf(float v) {
    if (fabsf(v) > 0.01f) return v > 0.0f ? 1.0f : 0.0f;
    return fmaf(v, 50.0f, 0.5f);
}

// ---------------- GEMM: P = Phi^T Phi ----------------
__global__ void k_phitphi64(const float* __restrict__ Phi) {
    if (blockIdx.x == 0 && blockIdx.y == 0 && threadIdx.x == 0 && threadIdx.y == 0)
        d_gamma = 1.0f;
    __shared__ float As[16][68];
    __shared__ float Bs[16][68];
    int ib = blockIdx.y * 64, jb = blockIdx.x * 64;
    int tx = threadIdx.x, ty = threadIdx.y;
    int t = ty * 16 + tx;
    float acc[4][4];
    #pragma unroll
    for (int r = 0; r < 4; r++)
        #pragma unroll
        for (int c = 0; c < 4; c++) acc[r][c] = 0.f;
    for (int k0 = 0; k0 < MDIM; k0 += 16) {
        #pragma unroll
        for (int q = t; q < 1024; q += 256) {
            int kk = q / 64, r = q % 64;
            As[kk][r] = (ib + r < NPIX) ? Phi[(k0 + kk) * NPIX + ib + r] : 0.f;
            Bs[kk][r] = (jb + r < NPIX) ? Phi[(k0 + kk) * NPIX + jb + r] : 0.f;
        }
        __syncthreads();
        #pragma unroll
        for (int kk = 0; kk < 16; kk++) {
            float4 a4 = *(const float4*)&As[kk][ty * 4];
            float4 b4 = *(const float4*)&Bs[kk][tx * 4];
            float ar[4] = {a4.x, a4.y, a4.z, a4.w};
            float br[4] = {b4.x, b4.y, b4.z, b4.w};
            #pragma unroll
            for (int r = 0; r < 4; r++)
                #pragma unroll
                for (int c = 0; c < 4; c++)
                    acc[r][c] = fmaf(ar[r], br[c], acc[r][c]);
        }
        __syncthreads();
    }
    #pragma unroll
    for (int r = 0; r < 4; r++) {
        int i = ib + ty * 4 + r;
        if (i >= NPIX) continue;
        #pragma unroll
        for (int c = 0; c < 4; c++) {
            int j = jb + tx * 4 + c;
            if (j < NPIX) d_P[i * NPIX + j] = acc[r][c];
        }
    }
}

// ---------------- phase GEMM: 32x64 tiles (144 CTAs = full wave) ----------------
__global__ void k_gemmP(const float* __restrict__ src, float* __restrict__ dst,
                        const float* __restrict__ alphas, int phase, int mode) {
    __shared__ float As[16][36];
    __shared__ float Bs[16][68];
    int bb = blockIdx.y * 32, jb = blockIdx.x * 64;
    int tx = threadIdx.x, ty = threadIdx.y;
    int t = ty * 16 + tx;
    float acc[2][4];
    #pragma unroll
    for (int r = 0; r < 2; r++)
        #pragma unroll
        for (int c = 0; c < 4; c++) acc[r][c] = 0.f;
    for (int k0 = 0; k0 < NPIX; k0 += 16) {
        #pragma unroll
        for (int q = t; q < 512; q += 256) {
            int r = q / 16, kk = q % 16;
            As[kk][r] = (k0 + kk < NPIX) ? src[(bb + r) * NPIX + k0 + kk] : 0.f;
        }
        #pragma unroll
        for (int q = t; q < 1024; q += 256) {
            int kk = q / 64, c = q % 64;
            Bs[kk][c] = (k0 + kk < NPIX && jb + c < NPIX) ? d_P[(k0 + kk) * NPIX + jb + c] : 0.f;
        }
        __syncthreads();
        #pragma unroll
        for (int kk = 0; kk < 16; kk++) {
            float a0 = As[kk][ty * 2], a1 = As[kk][ty * 2 + 1];
            float4 b4 = *(const float4*)&Bs[kk][tx * 4];
            float br[4] = {b4.x, b4.y, b4.z, b4.w};
            #pragma unroll
            for (int c = 0; c < 4; c++) {
                acc[0][c] = fmaf(a0, br[c], acc[0][c]);
                acc[1][c] = fmaf(a1, br[c], acc[1][c]);
            }
        }
        __syncthreads();
    }
    float alpha = fabsf(alphas[phase]);
    #pragma unroll
    for (int r = 0; r < 2; r++) {
        int b = bb + ty * 2 + r;
        #pragma unroll
        for (int c = 0; c < 4; c++) {
            int j = jb + tx * 4 + c;
            if (j < NPIX) {
                float dot = acc[r][c];
                float ptb = d_PhiTb[b * NPIX + j];
                if (mode == 0)
                    dst[b * NPIX + j] = src[b * NPIX + j] + alpha * (ptb - dot);
                else
                    dst[b * NPIX + j] = dot - ptb;
            }
        }
    }
}

__global__ void k_zstep(const float* __restrict__ x, float* __restrict__ z,
                        const float* __restrict__ alphas, int phase) {
    float alpha = fabsf(alphas[phase]);
    size_t base = (size_t)blockIdx.x * NPIX;
    for (int j = threadIdx.x; j < NPIX; j += blockDim.x)
        z[base + j] = x[base + j] - alpha * d_dotm[base + j];
}

__global__ void k_setupF(const float* __restrict__ Phix, const float* __restrict__ Phi,
                         const float* __restrict__ Qinit,
                         float* __restrict__ dPhiTb, float* __restrict__ dx) {
    __shared__ float As[32][33];
    __shared__ float Bs[32][33];
    int tmode = blockIdx.z;
    const float* Bsrc = tmode == 0 ? Phi : Qinit;
    float* dst = tmode == 0 ? dPhiTb : dx;
    int bb = blockIdx.y * 32, jb = blockIdx.x * 32;
    int tx = threadIdx.x, ty = threadIdx.y;
    int t = ty * 16 + tx;
    float acc00 = 0.f, acc01 = 0.f, acc10 = 0.f, acc11 = 0.f;
    for (int k0 = 0; k0 < MDIM; k0 += 32) {
        for (int q = t; q < 1024; q += 256) {
            int kk = q % 32, r = q / 32;
            As[kk][r] = (k0 + kk < MDIM) ? Phix[(bb + r) * MDIM + k0 + kk] : 0.f;
        }
        if (tmode == 0) {
            for (int q = t; q < 1024; q += 256) {
                int kk = q / 32, j = q % 32;
                Bs[kk][j] = (k0 + kk < MDIM && jb + j < NPIX) ? Bsrc[(k0 + kk) * NPIX + jb + j] : 0.f;
            }
        } else {
            for (int q = t; q < 1024; q += 256) {
                int kk = q % 32, j = q / 32;
                Bs[kk][j] = (k0 + kk < MDIM && jb + j < NPIX) ? Bsrc[(jb + j) * MDIM + k0 + kk] : 0.f;
            }
        }
        __syncthreads();
        #pragma unroll
        for (int kk = 0; kk < 32; kk++) {
            float a0 = As[kk][ty*2], a1 = As[kk][ty*2+1];
            float b0 = Bs[kk][tx*2], b1 = Bs[kk][tx*2+1];
            acc00 = fmaf(a0, b0, acc00); acc01 = fmaf(a0, b1, acc01);
            acc10 = fmaf(a1, b0, acc10); acc11 = fmaf(a1, b1, acc11);
        }
        __syncthreads();
    }
    int b0 = bb + ty*2, j0 = jb + tx*2;
    if (j0     < NPIX) dst[(b0  ) * NPIX + j0  ] = acc00;
    if (j0 + 1 < NPIX) dst[(b0  ) * NPIX + j0+1] = acc01;
    if (j0     < NPIX) dst[(b0+1) * NPIX + j0  ] = acc10;
    if (j0 + 1 < NPIX) dst[(b0+1) * NPIX + j0+1] = acc11;
}

// ---------------- tensor conv (32 -> 32) via mma.sync bf16 ----------------
// Weights staged fragment-major: [q][lane][4 u32], q = rI/4, rI = s*8 + nb*2 + j.
// FLAG_CONV1: input is z (f32); conv1 computed inline, x1 -> gmem, act(x1) -> rows.
__global__ __launch_bounds__(TC_THREADS) void k_convTC(
        const unsigned int* __restrict__ in, const float* __restrict__ w,
        unsigned int* __restrict__ out, const unsigned int* __restrict__ pre,
        const float* __restrict__ soft, int flags,
        const float* __restrict__ zin, const float* __restrict__ w1,
        unsigned int* __restrict__ x1out) {
    extern __shared__ char smem[];
    unsigned int* srows = (unsigned int*)(smem + OFF_ROWS);   // SROWS x ROWW u32
    uint32_t rows_addr = smem_to_u32(srows);
    const int dlt[9] = {-37,-36,-35,-1,0,1,35,36,37};
    int tid = threadIdx.x;
    int lane = tid & 31, warp = tid >> 5;
    int n = blockIdx.x;

    // zero input rows
    uint4 z4 = make_uint4(0, 0, 0, 0);
    for (int i = tid; i < SROWS * 5; i += TC_THREADS) ((uint4*)srows)[i] = z4;

    // stage weights directly into mma-fragment order
    bool flip = (flags & FLAG_FLIP) != 0;
    for (int idx = tid; idx < CC * CC * 9; idx += TC_THREADS) {
        int kx = idx % 3, ky = (idx / 3) % 3;
        int i = (idx / 9) % CC, o = idx / (9 * CC);
        float v = w[idx];
        int eci, eco, ek;
        if (flip) { eci = o; eco = i; ek = (2 - ky) * 3 + (2 - kx); }
        else      { eci = i; eco = o; ek = ky * 3 + kx; }
        int k = ek * 32 + eci;                // 0..287
        int s = k >> 4, r = k & 15, j = r >> 3, c = r & 7;
        int flane = ((eco & 7) << 2) | (c >> 1);
        int rI = s * 8 + ((eco >> 3) << 1) + j;
        *(__nv_bfloat16*)(smem + (rI >> 2) * 512 + flane * 16 + (rI & 3) * 4 + (c & 1) * 2)
            = __float2bfloat16(v);
    }

    if (flags & FLAG_CONV1) {
        // ---- conv1 fused: z f32 -> x1 (gmem bf16) + act(x1) (rows) ----
        float* s_z  = (float*)(smem + OFF_SZ);
        float* s_w1 = (float*)(smem + OFF_SW1);   // [k][co]
        for (int i = tid; i < SROWS; i += TC_THREADS) s_z[i] = 0.f;
        for (int i = tid; i < 9 * CC; i += TC_THREADS) {
            int o = i / 9, k = i % 9;
            s_w1[k * CC + o] = w1[i];
        }
        __syncthreads();
        const float* zb = zin + (size_t)n * NPIX;
        for (int p = tid; p < NPIX; p += TC_THREADS) {
            int y = p / 33, x = p - y * 33;
            s_z[FRONT + (y + 1) * 36 + (x + 1)] = zb[p];
        }
        __syncthreads();
        unsigned int* xo = x1out + (size_t)n * NPIX * 16;
        for (int p = tid; p < NPIX; p += TC_THREADS) {
            int y = p / 33, x = p - y * 33;
            int pp = FRONT + (y + 1) * 36 + (x + 1);
            float zv[9];
            #pragma unroll
            for (int k = 0; k < 9; k++) zv[k] = s_z[pp + dlt[k]];
            unsigned int* row = xo + p * 16;
            unsigned int* rw = srows + pp * ROWW;
            #pragma unroll 1
            for (int ch = 0; ch < 4; ch++) {
                float acc[8];
                #pragma unroll
                for (int j = 0; j < 8; j++) acc[j] = 0.f;
                #pragma unroll
                for (int k = 0; k < 9; k++) {
                    float4 w0 = *(const float4*)(s_w1 + k * CC + ch * 8);
                    float4 w1v = *(const float4*)(s_w1 + k * CC + ch * 8 + 4);
                    acc[0] = fmaf(zv[k], w0.x, acc[0]);
                    acc[1] = fmaf(zv[k], w0.y, acc[1]);
                    acc[2] = fmaf(zv[k], w0.z, acc[2]);
                    acc[3] = fmaf(zv[k], w0.w, acc[3]);
                    acc[4] = fmaf(zv[k], w1v.x, acc[4]);
                    acc[5] = fmaf(zv[k], w1v.y, acc[5]);
                    acc[6] = fmaf(zv[k], w1v.z, acc[6]);
                    acc[7] = fmaf(zv[k], w1v.w, acc[7]);
                }
                uint4 xv = make_uint4(bpk(acc[0], acc[1]), bpk(acc[2], acc[3]),
                                      bpk(acc[4], acc[5]), bpk(acc[6], acc[7]));
                *(uint4*)(row + ch * 4) = xv;
                uint4 av = make_uint4(bpk(actf(acc[0]), actf(acc[1])),
                                      bpk(actf(acc[2]), actf(acc[3])),
                                      bpk(actf(acc[4]), actf(acc[5])),
                                      bpk(actf(acc[6]), actf(acc[7])));
                *(uint4*)(rw + ch * 4) = av;
            }
        }
    } else {
        __syncthreads();
        // stage input pixels (fused act / gnorm)
        const uint4* inb = (const uint4*)in + (size_t)n * NPIX * 4;
        bool act_in = (flags & FLAG_ACT_IN) != 0;
        bool gn = (flags & FLAG_GNORM) != 0;
        float thr = 0.f, invthr = 0.f;
        if (gn) { thr = soft[0] * d_gamma; invthr = 1.0f / thr; }
        for (int p = tid; p < NPIX; p += TC_THREADS) {
            int y = p / 33, x = p - y * 33;
            int row = FRONT + (y + 1) * 36 + (x + 1);
            uint4 q0 = inb[p*4+0], q1 = inb[p*4+1], q2 = inb[p*4+2], q3 = inb[p*4+3];
            unsigned int u[16] = {q0.x,q0.y,q0.z,q0.w, q1.x,q1.y,q1.z,q1.w,
                                  q2.x,q2.y,q2.z,q2.w, q3.x,q3.y,q3.z,q3.w};
            if (act_in) {
                #pragma unroll
                for (int j = 0; j < 16; j++) {
                    float2 f = bupk(u[j]);
                    u[j] = bpk(actf(f.x), actf(f.y));
                }
            } else if (gn) {
                float2 f[16];
                float s = 0.f;
                #pragma unroll
                for (int j = 0; j < 16; j++) {
                    f[j] = bupk(u[j]);
                    s = fmaf(f[j].x, f[j].x, fmaf(f[j].y, f[j].y, s));
                }
                float nrm = sqrtf(s);
                float fac = (nrm > thr) ? (1.0f / fmaxf(nrm, 1e-12f)) : invthr;
                #pragma unroll
                for (int j = 0; j < 16; j++)
                    u[j] = bpk(f[j].x * fac, f[j].y * fac);
            }
            uint4* dst = (uint4*)(srows + row * ROWW);
            dst[0] = make_uint4(u[0],u[1],u[2],u[3]);
            dst[1] = make_uint4(u[4],u[5],u[6],u[7]);
            dst[2] = make_uint4(u[8],u[9],u[10],u[11]);
            dst[3] = make_uint4(u[12],u[13],u[14],u[15]);
        }
    }
    __syncthreads();

    // preload ALL B fragments via coalesced LDS.128 (fragment-major layout)
    uint32_t breg[144];
    {
        const uint4* fb = (const uint4*)smem;
        #pragma unroll
        for (int q = 0; q < 36; q++) {
            uint4 v = fb[q * 32 + lane];
            breg[q*4+0] = v.x; breg[q*4+1] = v.y;
            breg[q*4+2] = v.z; breg[q*4+3] = v.w;
        }
    }

    unsigned int* outp = out + (size_t)n * NPIX * 16;
    const unsigned int* prep = pre + (size_t)n * NPIX * 16;
    bool actder = (flags & FLAG_ACTDER) != 0;

    // dual-tile loop: tiles (base, base+8) per iteration for ILP
    for (int base = warp; base < NTILES; base += 16) {
        int t1 = base + 8;
        bool has2 = (t1 < NTILES);
        int p0a = base * 16, p0b = t1 * 16;
        int pla = p0a + (lane & 15); if (pla > NPIX - 1) pla = NPIX - 1;
        int plb = has2 ? (p0b + (lane & 15)) : pla;
        if (plb > NPIX - 1) plb = NPIX - 1;
        int ya = pla / 33, xa = pla - ya * 33;
        int yb = plb / 33, xb = plb - yb * 33;
        uint32_t abaseA = rows_addr + (uint32_t)((FRONT + (ya + 1) * 36 + (xa + 1)) * 80)
                        + (uint32_t)((lane >> 4) * 16);
        uint32_t abaseB = rows_addr + (uint32_t)((FRONT + (yb + 1) * 36 + (xb + 1)) * 80)
                        + (uint32_t)((lane >> 4) * 16);

        float dA[4][4], dB[4][4];
        #pragma unroll
        for (int nb = 0; nb < 4; nb++)
            #pragma unroll
            for (int j = 0; j < 4; j++) { dA[nb][j] = 0.f; dB[nb][j] = 0.f; }

        #pragma unroll
        for (int s = 0; s < KSTEPS; s++) {
            int t = s >> 1, h = s & 1;
            uint32_t off = (uint32_t)(dlt[t] * 80 + h * 32);
            uint32_t a0, a1, a2, a3, b0, b1, b2, b3;
            asm volatile("ldmatrix.sync.aligned.m8n8.x4.shared.b16 {%0,%1,%2,%3}, [%4];"
                         : "=r"(a0), "=r"(a1), "=r"(a2), "=r"(a3) : "r"(abaseA + off));
            asm volatile("ldmatrix.sync.aligned.m8n8.x4.shared.b16 {%0,%1,%2,%3}, [%4];"
                         : "=r"(b0), "=r"(b1), "=r"(b2), "=r"(b3) : "r"(abaseB + off));
            #pragma unroll
            for (int nb = 0; nb < 4; nb++) {
                uint32_t w0 = breg[s * 8 + nb * 2], w1r = breg[s * 8 + nb * 2 + 1];
                asm volatile(
                    "mma.sync.aligned.m16n8k16.row.col.f32.bf16.bf16.f32 "
                    "{%0,%1,%2,%3}, {%4,%5,%6,%7}, {%8,%9}, {%0,%1,%2,%3};"
                    : "+f"(dA[nb][0]), "+f"(dA[nb][1]), "+f"(dA[nb][2]), "+f"(dA[nb][3])
                    : "r"(a0), "r"(a1), "r"(a2), "r"(a3), "r"(w0), "r"(w1r));
                asm volatile(
                    "mma.sync.aligned.m16n8k16.row.col.f32.bf16.bf16.f32 "
                    "{%0,%1,%2,%3}, {%4,%5,%6,%7}, {%8,%9}, {%0,%1,%2,%3};"
                    : "+f"(dB[nb][0]), "+f"(dB[nb][1]), "+f"(dB[nb][2]), "+f"(dB[nb][3])
                    : "r"(b0), "r"(b1), "r"(b2), "r"(b3), "r"(w0), "r"(w1r));
            }
        }

        // epilogue tile A
        {
            int pA = p0a + (lane >> 2);
            int pB = pA + 8;
            #pragma unroll
            for (int nb = 0; nb < 4; nb++) {
                int ci = nb * 4 + (lane & 3);
                if (pA < NPIX) {
                    float c0 = dA[nb][0], c1 = dA[nb][1];
                    if (actder) {
                        float2 f = bupk(prep[pA * 16 + ci]);
                        c0 *= actdf(f.x); c1 *= actdf(f.y);
                    }
                    outp[pA * 16 + ci] = bpk(c0, c1);
                }
                if (pB < NPIX) {
                    float c2 = dA[nb][2], c3 = dA[nb][3];
                    if (actder) {
                        float2 f = bupk(prep[pB * 16 + ci]);
                        c2 *= actdf(f.x); c3 *= actdf(f.y);
                    }
                    outp[pB * 16 + ci] = bpk(c2, c3);
                }
            }
        }
        // epilogue tile B
        if (has2) {
            int pA = p0b + (lane >> 2);
            int pB = pA + 8;
            #pragma unroll
            for (int nb = 0; nb < 4; nb++) {
                int ci = nb * 4 + (lane & 3);
                if (pA < NPIX) {
                    float c0 = dB[nb][0], c1 = dB[nb][1];
                    if (actder) {
                        float2 f = bupk(prep[pA * 16 + ci]);
                        c0 *= actdf(f.x); c1 *= actdf(f.y);
                    }
                    outp[pA * 16 + ci] = bpk(c0, c1);
                }
                if (pB < NPIX) {
                    float c2 = dB[nb][2], c3 = dB[nb][3];
                    if (actder) {
                        float2 f = bupk(prep[pB * 16 + ci]);
                        c2 *= actdf(f.x); c3 *= actdf(f.y);
                    }
                    outp[pB * 16 + ci] = bpk(c2, c3);
                }
            }
        }
    }
}

// ---------------- convT1 (32 -> 1) from bf16 pixel-major, fused update ----------------
__global__ __launch_bounds__(T1_THREADS) void k_convT1n(
        const unsigned int* __restrict__ in, const float* __restrict__ w1,
        const float* __restrict__ z, float* __restrict__ x,
        const float* __restrict__ dotm, float* __restrict__ gphi,
        const float* __restrict__ alphas, const float* __restrict__ betas,
        int phase, int mode, float* __restrict__ out_extra) {
    extern __shared__ char smem[];
    unsigned int* srows = (unsigned int*)smem;     // SROWS * 16 u32
    __shared__ float s_w[CC * 9];                  // flipped [o][k]
    const int dlt[9] = {-37,-36,-35,-1,0,1,35,36,37};
    int n = blockIdx.x, tid = threadIdx.x;

    uint4 z4 = make_uint4(0, 0, 0, 0);
    for (int i = tid; i < SROWS * 4; i += T1_THREADS) ((uint4*)srows)[i] = z4;
    for (int idx = tid; idx < CC * 9; idx += T1_THREADS) {
        int o = idx / 9, k = idx % 9;
        int ky = k / 3, kx = k % 3;
        s_w[o * 9 + (2 - ky) * 3 + (2 - kx)] = w1[idx];
    }
    __syncthreads();
    const uint4* inb = (const uint4*)in + (size_t)n * NPIX * 4;
    for (int p = tid; p < NPIX; p += T1_THREADS) {
        int y = p / 33, xx = p - y * 33;
        int row = FRONT + (y + 1) * 36 + (xx + 1);
        uint4* dst = (uint4*)(srows + row * 16);
        dst[0] = inb[p*4+0]; dst[1] = inb[p*4+1];
        dst[2] = inb[p*4+2]; dst[3] = inb[p*4+3];
    }
    __syncthreads();

    float a = fabsf(alphas[phase]), b = fabsf(betas[phase]);
    float tau = a * b / (a + b);

    for (int p = tid; p < NPIX; p += T1_THREADS) {
        int y = p / 33, xx = p - y * 33;
        int pp = FRONT + (y + 1) * 36 + (xx + 1);
        float acc = 0.f;
        #pragma unroll
        for (int k = 0; k < 9; k++) {
            const uint4* rp = (const uint4*)(srows + (pp + dlt[k]) * 16);
            uint4 r0 = rp[0], r1 = rp[1], r2 = rp[2], r3 = rp[3];
            unsigned int u[16] = {r0.x,r0.y,r0.z,r0.w, r1.x,r1.y,r1.z,r1.w,
                                  r2.x,r2.y,r2.z,r2.w, r3.x,r3.y,r3.z,r3.w};
            #pragma unroll
            for (int j = 0; j < 16; j++) {
                float2 f = bupk(u[j]);
                acc = fmaf(f.x, s_w[(2*j) * 9 + k], acc);
                acc = fmaf(f.y, s_w[(2*j+1) * 9 + k], acc);
            }
        }
        size_t off = (size_t)n * NPIX + p;
        if (mode == 0) {
            float nx = z[off] - tau * acc;
            x[off] = nx;
            if (out_extra) out_extra[off] = nx;
        } else {
            gphi[off] = dotm[off] + acc;
        }
    }
}

// ---------------- row norms + gamma update ----------------
__global__ void k_rownorm(const float* __restrict__ gphi) {
    __shared__ float red[256];
    int bidx = blockIdx.x;
    float s = 0.f;
    for (int j = threadIdx.x; j < NPIX; j += 256) {
        float v = gphi[(size_t)bidx * NPIX + j];
        s = fmaf(v, v, s);
    }
    red[threadIdx.x] = s;
    __syncthreads();
    for (int off = 128; off > 0; off >>= 1) {
        if (threadIdx.x < off) red[threadIdx.x] += red[threadIdx.x + off];
        __syncthreads();
    }
    if (threadIdx.x == 0) d_ngrad[bidx] = sqrtf(red[0]);
}

__global__ void k_gamma(const float* __restrict__ soft_thr) {
    __shared__ float red[256];
    red[threadIdx.x] = d_ngrad[threadIdx.x];
    __syncthreads();
    for (int off = 128; off > 0; off >>= 1) {
        if (threadIdx.x < off) red[threadIdx.x] += red[threadIdx.x + off];
        __syncthreads();
    }
    if (threadIdx.x == 0) {
        float mean = red[0] / (float)BB;
        float g = d_gamma;
        if (mean < 15000.0f * g * soft_thr[0]) g *= 0.9f;
        d_gamma = g;
    }
}

// ---------------- host orchestration ----------------
static void grad_r_chain(const float* src, const float* c1, const float* c2,
                         const float* c3, const float* c4, const float* soft,
                         unsigned int* px1, unsigned int* px2, unsigned int* px3,
                         unsigned int* pg, unsigned int* pbA,
                         const float* pz, float* px, const float* pdotm, float* pgphi,
                         const float* alphas, const float* betas,
                         int phase, int mode, float* out_extra) {
    k_convTC<<<BB, TC_THREADS, SMEM_TC2>>>(px1, c2, px2, px1, soft, FLAG_CONV1,
                                           src, c1, px1);
    k_convTC<<<BB, TC_THREADS, SMEM_TC>>>(px2, c3, px3, px1, soft, FLAG_ACT_IN,
                                          nullptr, nullptr, nullptr);
    k_convTC<<<BB, TC_THREADS, SMEM_TC>>>(px3, c4, pg,  px1, soft, FLAG_ACT_IN,
                                          nullptr, nullptr, nullptr);
    k_convTC<<<BB, TC_THREADS, SMEM_TC>>>(pg,  c4, pbA, px3, soft,
                                          FLAG_FLIP | FLAG_ACTDER | FLAG_GNORM,
                                          nullptr, nullptr, nullptr);
    k_convTC<<<BB, TC_THREADS, SMEM_TC>>>(pbA, c3, pg,  px2, soft,
                                          FLAG_FLIP | FLAG_ACTDER,
                                          nullptr, nullptr, nullptr);
    k_convTC<<<BB, TC_THREADS, SMEM_TC>>>(pg,  c2, pbA, px1, soft,
                                          FLAG_FLIP | FLAG_ACTDER,
                                          nullptr, nullptr, nullptr);
    k_convT1n<<<BB, T1_THREADS, SMEM_T1N>>>(pbA, c1, pz, px, pdotm, pgphi,
                                            alphas, betas, phase, mode, out_extra);
}

extern "C" void kernel_launch(void* const* d_in, const int* in_sizes, int n_in,
                              void* d_out, int out_size) {
    (void)in_sizes; (void)n_in; (void)out_size;
    const float* Phix   = (const float*)d_in[0];
    const float* Phi    = (const float*)d_in[1];
    const float* Qinit  = (const float*)d_in[2];
    const float* soft   = (const float*)d_in[3];
    const float* alphas = (const float*)d_in[4];
    const float* betas  = (const float*)d_in[5];
    const float* c1     = (const float*)d_in[6];
    const float* c2     = (const float*)d_in[7];
    const float* c3     = (const float*)d_in[8];
    const float* c4     = (const float*)d_in[9];
    float* out = (float*)d_out;

    cudaFuncSetAttribute(k_convTC,  cudaFuncAttributeMaxDynamicSharedMemorySize, SMEM_TC2);
    cudaFuncSetAttribute(k_convT1n, cudaFuncAttributeMaxDynamicSharedMemorySize, SMEM_T1N);

    float *px, *pz, *pgphi, *pdotm, *pPhiTb;
    unsigned int *px1, *px2, *px3, *pg, *pbA;
    cudaGetSymbolAddress((void**)&px,     d_x);
    cudaGetSymbolAddress((void**)&pz,     d_z);
    cudaGetSymbolAddress((void**)&pgphi,  d_gphi);
    cudaGetSymbolAddress((void**)&pdotm,  d_dotm);
    cudaGetSymbolAddress((void**)&px1,    d_x1);
    cudaGetSymbolAddress((void**)&px2,    d_x2);
    cudaGetSymbolAddress((void**)&px3,    d_x3);
    cudaGetSymbolAddress((void**)&pg,     d_g);
    cudaGetSymbolAddress((void**)&pbA,    d_bA);
    cudaGetSymbolAddress((void**)&pPhiTb, d_PhiTb);

    dim3 tb16(16, 16);
    k_phitphi64<<<dim3(18, 18), tb16>>>(Phi);                       // + gamma init
    k_setupF<<<dim3(35, 8, 2), tb16>>>(Phix, Phi, Qinit, pPhiTb, px);

    for (int p = 0; p < 3; p++) {
        if (p == 0)
            k_gemmP<<<dim3(18, 8), tb16>>>(px, pz, alphas, p, 0);
        else
            k_zstep<<<BB, 256>>>(px, pz, alphas, p);
        grad_r_chain(pz, c1, c2, c3, c4, soft, px1, px2, px3, pg, pbA,
                     pz, px, pdotm, pgphi, alphas, betas, p, 0,
                     (p == 2) ? out : nullptr);
        if (p < 2) {
            k_gemmP<<<dim3(18, 8), tb16>>>(px, pdotm, alphas, p, 1);
            grad_r_chain(px, c1, c2, c3, c4, soft, px1, px2, px3, pg, pbA,
                         pz, px, pdotm, pgphi, alphas, betas, p, 1, nullptr);
            k_rownorm<<<BB, 256>>>(pgphi);
            k_gamma<<<1, 256>>>(soft);
        }
    }
}

// round 14
// speedup vs baseline: 1.0427x; 1.0427x over previous
#include <cuda_runtime.h>
#include <cuda_bf16.h>
#include <math.h>
#include <cstdint>

#define BB   256
#define NPIX 1089
#define MDIM 272
#define CC   32

#define FLAG_ACT_IN 1
#define FLAG_FLIP   2
#define FLAG_ACTDER 4
#define FLAG_GNORM  8
#define FLAG_CONV1  16

// tensor-conv geometry (half-image CTAs)
#define TC_THREADS 256
#define T1_THREADS 256
#define FRONT   40            /* u32-row entries of margin before local row 0 */
#define HROWS   800           /* local pixel-position slots per half buffer */
#define SROWS   1360          /* full-image buffer (convT1n) */
#define ROWW    20            /* u32 per position (80B stride, conflict-free ldmatrix) */
#define NTILES  69            /* ceil(1089/16) pixel tiles */
#define TSPLIT  35            /* half 0: tiles [0,35), half 1: [35,69) */
#define KSTEPS  18            /* 9 taps * 32 ci / 16 */
#define WT_STRIDE 290         /* bf16 per Wt row (32 co rows) */

#define OFF_ROWS (CC * WT_STRIDE * 2)            /* 18560 */
#define SMEM_TCH (OFF_ROWS + HROWS * ROWW * 4)   /* 82560 */
#define OFF_SZ   SMEM_TCH
#define OFF_SW1  (OFF_SZ + HROWS * 4)            /* 85760 */
#define SMEM_TCH2 (OFF_SW1 + 9 * CC * 4)         /* 86912 */
#define SMEM_T1N (SROWS * 64)                    /* 87040 */

// ---------------- device state (static, no allocation) ----------------
__device__ float d_P[NPIX*NPIX];
__device__ float d_PhiTb[BB*NPIX];
__device__ float d_x[BB*NPIX];
__device__ float d_z[BB*NPIX];
__device__ float d_gphi[BB*NPIX];
__device__ float d_dotm[BB*NPIX];
// pixel-major bf16 tensors: [image][pixel][32ch] as 16 u32 per pixel
__device__ unsigned int d_x1[BB*NPIX*16];
__device__ unsigned int d_x2[BB*NPIX*16];
__device__ unsigned int d_x3[BB*NPIX*16];
__device__ unsigned int d_g [BB*NPIX*16];
__device__ unsigned int d_bA[BB*NPIX*16];
__device__ float d_ngrad[BB];
__device__ float d_gamma;

__device__ __forceinline__ uint32_t smem_to_u32(const void* p) {
    uint32_t a;
    asm("{ .reg .u64 t; cvta.to.shared.u64 t, %1; cvt.u32.u64 %0, t; }" : "=r"(a) : "l"(p));
    return a;
}

// ---------------- bf16 pack/unpack ----------------
__device__ __forceinline__ float2 bupk(unsigned int u) {
    __nv_bfloat162 t = *reinterpret_cast<__nv_bfloat162*>(&u);
    return __bfloat1622float2(t);
}
__device__ __forceinline__ unsigned int bpk(float a, float b) {
    __nv_bfloat162 t = __floats2bfloat162_rn(a, b);
    return *reinterpret_cast<unsigned int*>(&t);
}

// ---------------- activation (eq. 33), DELTA = 0.01 ----------------
__device__ __forceinline__ float actf(float v) {
    if (fabsf(v) > 0.01f) return fmaxf(v, 0.0f);
    return fmaf(v*v, 25.0f, fmaf(v, 0.5f, 0.0025f));
}
__device__ __forceinline__ float actdf(float v) {
    if (fabsf(v) > 0.01f) return v > 0.0f ? 1.0f : 0.0f;
    return fmaf(v, 50.0f, 0.5f);
}

// ---------------- GEMM: P = Phi^T Phi ----------------
__global__ void k_phitphi64(const float* __restrict__ Phi) {
    if (blockIdx.x == 0 && blockIdx.y == 0 && threadIdx.x == 0 && threadIdx.y == 0)
        d_gamma = 1.0f;
    __shared__ float As[16][68];
    __shared__ float Bs[16][68];
    int ib = blockIdx.y * 64, jb = blockIdx.x * 64;
    int tx = threadIdx.x, ty = threadIdx.y;
    int t = ty * 16 + tx;
    float acc[4][4];
    #pragma unroll
    for (int r = 0; r < 4; r++)
        #pragma unroll
        for (int c = 0; c < 4; c++) acc[r][c] = 0.f;
    for (int k0 = 0; k0 < MDIM; k0 += 16) {
        #pragma unroll
        for (int q = t; q < 1024; q += 256) {
            int kk = q / 64, r = q % 64;
            As[kk][r] = (ib + r < NPIX) ? Phi[(k0 + kk) * NPIX + ib + r] : 0.f;
            Bs[kk][r] = (jb + r < NPIX) ? Phi[(k0 + kk) * NPIX + jb + r] : 0.f;
        }
        __syncthreads();
        #pragma unroll
        for (int kk = 0; kk < 16; kk++) {
            float4 a4 = *(const float4*)&As[kk][ty * 4];
            float4 b4 = *(const float4*)&Bs[kk][tx * 4];
            float ar[4] = {a4.x, a4.y, a4.z, a4.w};
            float br[4] = {b4.x, b4.y, b4.z, b4.w};
            #pragma unroll
            for (int r = 0; r < 4; r++)
                #pragma unroll
                for (int c = 0; c < 4; c++)
                    acc[r][c] = fmaf(ar[r], br[c], acc[r][c]);
        }
        __syncthreads();
    }
    #pragma unroll
    for (int r = 0; r < 4; r++) {
        int i = ib + ty * 4 + r;
        if (i >= NPIX) continue;
        #pragma unroll
        for (int c = 0; c < 4; c++) {
            int j = jb + tx * 4 + c;
            if (j < NPIX) d_P[i * NPIX + j] = acc[r][c];
        }
    }
}

// ---------------- phase GEMM: 32x64 tiles (144 CTAs = full wave) ----------------
__global__ void k_gemmP(const float* __restrict__ src, float* __restrict__ dst,
                        const float* __restrict__ alphas, int phase, int mode) {
    __shared__ float As[16][36];
    __shared__ float Bs[16][68];
    int bb = blockIdx.y * 32, jb = blockIdx.x * 64;
    int tx = threadIdx.x, ty = threadIdx.y;
    int t = ty * 16 + tx;
    float acc[2][4];
    #pragma unroll
    for (int r = 0; r < 2; r++)
        #pragma unroll
        for (int c = 0; c < 4; c++) acc[r][c] = 0.f;
    for (int k0 = 0; k0 < NPIX; k0 += 16) {
        #pragma unroll
        for (int q = t; q < 512; q += 256) {
            int r = q / 16, kk = q % 16;
            As[kk][r] = (k0 + kk < NPIX) ? src[(bb + r) * NPIX + k0 + kk] : 0.f;
        }
        #pragma unroll
        for (int q = t; q < 1024; q += 256) {
            int kk = q / 64, c = q % 64;
            Bs[kk][c] = (k0 + kk < NPIX && jb + c < NPIX) ? d_P[(k0 + kk) * NPIX + jb + c] : 0.f;
        }
        __syncthreads();
        #pragma unroll
        for (int kk = 0; kk < 16; kk++) {
            float a0 = As[kk][ty * 2], a1 = As[kk][ty * 2 + 1];
            float4 b4 = *(const float4*)&Bs[kk][tx * 4];
            float br[4] = {b4.x, b4.y, b4.z, b4.w};
            #pragma unroll
            for (int c = 0; c < 4; c++) {
                acc[0][c] = fmaf(a0, br[c], acc[0][c]);
                acc[1][c] = fmaf(a1, br[c], acc[1][c]);
            }
        }
        __syncthreads();
    }
    float alpha = fabsf(alphas[phase]);
    #pragma unroll
    for (int r = 0; r < 2; r++) {
        int b = bb + ty * 2 + r;
        #pragma unroll
        for (int c = 0; c < 4; c++) {
            int j = jb + tx * 4 + c;
            if (j < NPIX) {
                float dot = acc[r][c];
                float ptb = d_PhiTb[b * NPIX + j];
                if (mode == 0)
                    dst[b * NPIX + j] = src[b * NPIX + j] + alpha * (ptb - dot);
                else
                    dst[b * NPIX + j] = dot - ptb;
            }
        }
    }
}

__global__ void k_zstep(const float* __restrict__ x, float* __restrict__ z,
                        const float* __restrict__ alphas, int phase) {
    float alpha = fabsf(alphas[phase]);
    size_t base = (size_t)blockIdx.x * NPIX;
    for (int j = threadIdx.x; j < NPIX; j += blockDim.x)
        z[base + j] = x[base + j] - alpha * d_dotm[base + j];
}

__global__ void k_setupF(const float* __restrict__ Phix, const float* __restrict__ Phi,
                         const float* __restrict__ Qinit,
                         float* __restrict__ dPhiTb, float* __restrict__ dx) {
    __shared__ float As[32][33];
    __shared__ float Bs[32][33];
    int tmode = blockIdx.z;
    const float* Bsrc = tmode == 0 ? Phi : Qinit;
    float* dst = tmode == 0 ? dPhiTb : dx;
    int bb = blockIdx.y * 32, jb = blockIdx.x * 32;
    int tx = threadIdx.x, ty = threadIdx.y;
    int t = ty * 16 + tx;
    float acc00 = 0.f, acc01 = 0.f, acc10 = 0.f, acc11 = 0.f;
    for (int k0 = 0; k0 < MDIM; k0 += 32) {
        for (int q = t; q < 1024; q += 256) {
            int kk = q % 32, r = q / 32;
            As[kk][r] = (k0 + kk < MDIM) ? Phix[(bb + r) * MDIM + k0 + kk] : 0.f;
        }
        if (tmode == 0) {
            for (int q = t; q < 1024; q += 256) {
                int kk = q / 32, j = q % 32;
                Bs[kk][j] = (k0 + kk < MDIM && jb + j < NPIX) ? Bsrc[(k0 + kk) * NPIX + jb + j] : 0.f;
            }
        } else {
            for (int q = t; q < 1024; q += 256) {
                int kk = q % 32, j = q / 32;
                Bs[kk][j] = (k0 + kk < MDIM && jb + j < NPIX) ? Bsrc[(jb + j) * MDIM + k0 + kk] : 0.f;
            }
        }
        __syncthreads();
        #pragma unroll
        for (int kk = 0; kk < 32; kk++) {
            float a0 = As[kk][ty*2], a1 = As[kk][ty*2+1];
            float b0 = Bs[kk][tx*2], b1 = Bs[kk][tx*2+1];
            acc00 = fmaf(a0, b0, acc00); acc01 = fmaf(a0, b1, acc01);
            acc10 = fmaf(a1, b0, acc10); acc11 = fmaf(a1, b1, acc11);
        }
        __syncthreads();
    }
    int b0 = bb + ty*2, j0 = jb + tx*2;
    if (j0     < NPIX) dst[(b0  ) * NPIX + j0  ] = acc00;
    if (j0 + 1 < NPIX) dst[(b0  ) * NPIX + j0+1] = acc01;
    if (j0     < NPIX) dst[(b0+1) * NPIX + j0  ] = acc10;
    if (j0 + 1 < NPIX) dst[(b0+1) * NPIX + j0+1] = acc11;
}

// ---------------- tensor conv (32 -> 32) via mma.sync bf16, half-image CTAs ---------
// blockIdx.x = image, blockIdx.y = half (rbase = h*16).
// FLAG_CONV1: input is z (f32); conv1 computed inline, x1 -> gmem, act(x1) -> rows.
__global__ __launch_bounds__(TC_THREADS) void k_convTC(
        const unsigned int* __restrict__ in, const float* __restrict__ w,
        unsigned int* __restrict__ out, const unsigned int* __restrict__ pre,
        const float* __restrict__ soft, int flags,
        const float* __restrict__ zin, const float* __restrict__ w1,
        unsigned int* __restrict__ x1out) {
    extern __shared__ char smem[];
    __nv_bfloat16* wt = (__nv_bfloat16*)smem;                 // [32][WT_STRIDE]
    unsigned int* srows = (unsigned int*)(smem + OFF_ROWS);   // HROWS x ROWW u32
    uint32_t rows_addr = smem_to_u32(srows);
    const int dlt[9] = {-37,-36,-35,-1,0,1,35,36,37};
    int tid = threadIdx.x;
    int lane = tid & 31, warp = tid >> 5;
    int n = blockIdx.x;
    int h = blockIdx.y;
    int rbase = h * 16;                 // stored-row (y+1) base of local buffer
    int lbase = FRONT - rbase * 36;     // local pos = lbase + (y+1)*36 + (x+1)

    // zero local rows buffer
    uint4 z4 = make_uint4(0, 0, 0, 0);
    for (int i = tid; i < HROWS * 5; i += TC_THREADS) ((uint4*)srows)[i] = z4;

    // stage weights transposed: Wt[co][tap*32+ci]
    bool flip = (flags & FLAG_FLIP) != 0;
    for (int idx = tid; idx < CC * CC * 9; idx += TC_THREADS) {
        int kx = idx % 3, ky = (idx / 3) % 3;
        int i = (idx / 9) % CC, o = idx / (9 * CC);
        float v = w[idx];
        int eci, eco, ek;
        if (flip) { eci = o; eco = i; ek = (2 - ky) * 3 + (2 - kx); }
        else      { eci = i; eco = o; ek = ky * 3 + kx; }
        wt[eco * WT_STRIDE + ek * 32 + eci] = __float2bfloat16(v);
    }

    // pixel rows this half must have staged: y in [rbase-1, rbase+18] clamped
    int ylo = rbase - 1; if (ylo < 0) ylo = 0;
    int yhi = rbase + 18; if (yhi > 32) yhi = 32;

    if (flags & FLAG_CONV1) {
        // ---- conv1 fused: z f32 -> x1 (gmem bf16) + act(x1) (rows) ----
        float* s_z  = (float*)(smem + OFF_SZ);
        float* s_w1 = (float*)(smem + OFF_SW1);   // [k][co]
        for (int i = tid; i < HROWS; i += TC_THREADS) s_z[i] = 0.f;
        for (int i = tid; i < 9 * CC; i += TC_THREADS) {
            int o = i / 9, k = i % 9;
            s_w1[k * CC + o] = w1[i];
        }
        __syncthreads();
        const float* zb = zin + (size_t)n * NPIX;
        int zlo = ylo - 1; if (zlo < 0) zlo = 0;
        int zhi = yhi + 1; if (zhi > 32) zhi = 32;
        for (int p = zlo * 33 + tid; p < (zhi + 1) * 33; p += TC_THREADS) {
            int y = p / 33, x = p - y * 33;
            s_z[lbase + (y + 1) * 36 + (x + 1)] = zb[p];
        }
        __syncthreads();
        unsigned int* xo = x1out + (size_t)n * NPIX * 16;
        for (int p = ylo * 33 + tid; p < (yhi + 1) * 33; p += TC_THREADS) {
            int y = p / 33, x = p - y * 33;
            int pp = lbase + (y + 1) * 36 + (x + 1);
            float zv[9];
            #pragma unroll
            for (int k = 0; k < 9; k++) zv[k] = s_z[pp + dlt[k]];
            unsigned int* row = xo + p * 16;
            unsigned int* rw = srows + pp * ROWW;
            #pragma unroll 1
            for (int ch = 0; ch < 4; ch++) {
                float acc[8];
                #pragma unroll
                for (int j = 0; j < 8; j++) acc[j] = 0.f;
                #pragma unroll
                for (int k = 0; k < 9; k++) {
                    float4 w0 = *(const float4*)(s_w1 + k * CC + ch * 8);
                    float4 w1v = *(const float4*)(s_w1 + k * CC + ch * 8 + 4);
                    acc[0] = fmaf(zv[k], w0.x, acc[0]);
                    acc[1] = fmaf(zv[k], w0.y, acc[1]);
                    acc[2] = fmaf(zv[k], w0.z, acc[2]);
                    acc[3] = fmaf(zv[k], w0.w, acc[3]);
                    acc[4] = fmaf(zv[k], w1v.x, acc[4]);
                    acc[5] = fmaf(zv[k], w1v.y, acc[5]);
                    acc[6] = fmaf(zv[k], w1v.z, acc[6]);
                    acc[7] = fmaf(zv[k], w1v.w, acc[7]);
                }
                uint4 xv = make_uint4(bpk(acc[0], acc[1]), bpk(acc[2], acc[3]),
                                      bpk(acc[4], acc[5]), bpk(acc[6], acc[7]));
                *(uint4*)(row + ch * 4) = xv;
                uint4 av = make_uint4(bpk(actf(acc[0]), actf(acc[1])),
                                      bpk(actf(acc[2]), actf(acc[3])),
                                      bpk(actf(acc[4]), actf(acc[5])),
                                      bpk(actf(acc[6]), actf(acc[7])));
                *(uint4*)(rw + ch * 4) = av;
            }
        }
    } else {
        __syncthreads();
        // stage input pixels (fused act / gnorm)
        const uint4* inb = (const uint4*)in + (size_t)n * NPIX * 4;
        bool act_in = (flags & FLAG_ACT_IN) != 0;
        bool gn = (flags & FLAG_GNORM) != 0;
        float thr = 0.f, invthr = 0.f;
        if (gn) { thr = soft[0] * d_gamma; invthr = 1.0f / thr; }
        for (int p = ylo * 33 + tid; p < (yhi + 1) * 33; p += TC_THREADS) {
            int y = p / 33, x = p - y * 33;
            int row = lbase + (y + 1) * 36 + (x + 1);
            uint4 q0 = inb[p*4+0], q1 = inb[p*4+1], q2 = inb[p*4+2], q3 = inb[p*4+3];
            unsigned int u[16] = {q0.x,q0.y,q0.z,q0.w, q1.x,q1.y,q1.z,q1.w,
                                  q2.x,q2.y,q2.z,q2.w, q3.x,q3.y,q3.z,q3.w};
            if (act_in) {
                #pragma unroll
                for (int j = 0; j < 16; j++) {
                    float2 f = bupk(u[j]);
                    u[j] = bpk(actf(f.x), actf(f.y));
                }
            } else if (gn) {
                float2 f[16];
                float s = 0.f;
                #pragma unroll
                for (int j = 0; j < 16; j++) {
                    f[j] = bupk(u[j]);
                    s = fmaf(f[j].x, f[j].x, fmaf(f[j].y, f[j].y, s));
                }
                float nrm = sqrtf(s);
                float fac = (nrm > thr) ? (1.0f / fmaxf(nrm, 1e-12f)) : invthr;
                #pragma unroll
                for (int j = 0; j < 16; j++)
                    u[j] = bpk(f[j].x * fac, f[j].y * fac);
            }
            uint4* dst = (uint4*)(srows + row * ROWW);
            dst[0] = make_uint4(u[0],u[1],u[2],u[3]);
            dst[1] = make_uint4(u[4],u[5],u[6],u[7]);
            dst[2] = make_uint4(u[8],u[9],u[10],u[11]);
            dst[3] = make_uint4(u[12],u[13],u[14],u[15]);
        }
    }
    __syncthreads();

    // preload ALL B fragments into registers (tile-invariant)
    uint32_t breg[KSTEPS][4][2];
    {
        int brow = lane >> 2, bcol = (lane & 3) * 2;
        #pragma unroll
        for (int s = 0; s < KSTEPS; s++) {
            #pragma unroll
            for (int nb = 0; nb < 4; nb++) {
                const __nv_bfloat16* wr = wt + (nb * 8 + brow) * WT_STRIDE + s * 16 + bcol;
                breg[s][nb][0] = *(const uint32_t*)wr;
                breg[s][nb][1] = *(const uint32_t*)(wr + 8);
            }
        }
    }

    unsigned int* outp = out + (size_t)n * NPIX * 16;
    const unsigned int* prep = pre + (size_t)n * NPIX * 16;
    bool actder = (flags & FLAG_ACTDER) != 0;

    int tstart = h ? TSPLIT : 0;
    int tend   = h ? NTILES : TSPLIT;

    for (int tile = tstart + warp; tile < tend; tile += 8) {
        int p0 = tile * 16;
        int pl = p0 + (lane & 15); if (pl > NPIX - 1) pl = NPIX - 1;
        int y = pl / 33, x = pl - y * 33;
        uint32_t abase = rows_addr
                       + (uint32_t)((lbase + (y + 1) * 36 + (x + 1)) * 80)
                       + (uint32_t)((lane >> 4) * 16);

        float d[4][4];
        #pragma unroll
        for (int nb = 0; nb < 4; nb++)
            #pragma unroll
            for (int j = 0; j < 4; j++) d[nb][j] = 0.f;

        #pragma unroll
        for (int s = 0; s < KSTEPS; s++) {
            int t = s >> 1, hh = s & 1;
            uint32_t aaddr = abase + (uint32_t)(dlt[t] * 80 + hh * 32);
            uint32_t a0, a1, a2, a3;
            asm volatile("ldmatrix.sync.aligned.m8n8.x4.shared.b16 {%0,%1,%2,%3}, [%4];"
                         : "=r"(a0), "=r"(a1), "=r"(a2), "=r"(a3) : "r"(aaddr));
            #pragma unroll
            for (int nb = 0; nb < 4; nb++) {
                asm volatile(
                    "mma.sync.aligned.m16n8k16.row.col.f32.bf16.bf16.f32 "
                    "{%0,%1,%2,%3}, {%4,%5,%6,%7}, {%8,%9}, {%0,%1,%2,%3};"
                    : "+f"(d[nb][0]), "+f"(d[nb][1]), "+f"(d[nb][2]), "+f"(d[nb][3])
                    : "r"(a0), "r"(a1), "r"(a2), "r"(a3),
                      "r"(breg[s][nb][0]), "r"(breg[s][nb][1]));
            }
        }

        // epilogue: D (16x32 f32) -> pixel-major bf16 u32
        int pA = p0 + (lane >> 2);
        int pB = pA + 8;
        #pragma unroll
        for (int nb = 0; nb < 4; nb++) {
            int ci = nb * 4 + (lane & 3);     // u32 (co-pair) index within pixel
            if (pA < NPIX) {
                float c0 = d[nb][0], c1 = d[nb][1];
                if (actder) {
                    float2 f = bupk(prep[pA * 16 + ci]);
                    c0 *= actdf(f.x); c1 *= actdf(f.y);
                }
                outp[pA * 16 + ci] = bpk(c0, c1);
            }
            if (pB < NPIX) {
                float c2 = d[nb][2], c3 = d[nb][3];
                if (actder) {
                    float2 f = bupk(prep[pB * 16 + ci]);
                    c2 *= actdf(f.x); c3 *= actdf(f.y);
                }
                outp[pB * 16 + ci] = bpk(c2, c3);
            }
        }
    }
}

// ---------------- convT1 (32 -> 1) from bf16 pixel-major, fused update ----------------
__global__ __launch_bounds__(T1_THREADS) void k_convT1n(
        const unsigned int* __restrict__ in, const float* __restrict__ w1,
        const float* __restrict__ z, float* __restrict__ x,
        const float* __restrict__ dotm, float* __restrict__ gphi,
        const float* __restrict__ alphas, const float* __restrict__ betas,
        int phase, int mode, float* __restrict__ out_extra) {
    extern __shared__ char smem[];
    unsigned int* srows = (unsigned int*)smem;     // SROWS * 16 u32
    __shared__ float s_w[CC * 9];                  // flipped [o][k]
    const int dlt[9] = {-37,-36,-35,-1,0,1,35,36,37};
    int n = blockIdx.x, tid = threadIdx.x;

    uint4 z4 = make_uint4(0, 0, 0, 0);
    for (int i = tid; i < SROWS * 4; i += T1_THREADS) ((uint4*)srows)[i] = z4;
    for (int idx = tid; idx < CC * 9; idx += T1_THREADS) {
        int o = idx / 9, k = idx % 9;
        int ky = k / 3, kx = k % 3;
        s_w[o * 9 + (2 - ky) * 3 + (2 - kx)] = w1[idx];
    }
    __syncthreads();
    const uint4* inb = (const uint4*)in + (size_t)n * NPIX * 4;
    for (int p = tid; p < NPIX; p += T1_THREADS) {
        int y = p / 33, xx = p - y * 33;
        int row = FRONT + (y + 1) * 36 + (xx + 1);
        uint4* dst = (uint4*)(srows + row * 16);
        dst[0] = inb[p*4+0]; dst[1] = inb[p*4+1];
        dst[2] = inb[p*4+2]; dst[3] = inb[p*4+3];
    }
    __syncthreads();

    float a = fabsf(alphas[phase]), b = fabsf(betas[phase]);
    float tau = a * b / (a + b);

    for (int p = tid; p < NPIX; p += T1_THREADS) {
        int y = p / 33, xx = p - y * 33;
        int pp = FRONT + (y + 1) * 36 + (xx + 1);
        float acc = 0.f;
        #pragma unroll
        for (int k = 0; k < 9; k++) {
            const uint4* rp = (const uint4*)(srows + (pp + dlt[k]) * 16);
            uint4 r0 = rp[0], r1 = rp[1], r2 = rp[2], r3 = rp[3];
            unsigned int u[16] = {r0.x,r0.y,r0.z,r0.w, r1.x,r1.y,r1.z,r1.w,
                                  r2.x,r2.y,r2.z,r2.w, r3.x,r3.y,r3.z,r3.w};
            #pragma unroll
            for (int j = 0; j < 16; j++) {
                float2 f = bupk(u[j]);
                acc = fmaf(f.x, s_w[(2*j) * 9 + k], acc);
                acc = fmaf(f.y, s_w[(2*j+1) * 9 + k], acc);
            }
        }
        size_t off = (size_t)n * NPIX + p;
        if (mode == 0) {
            float nx = z[off] - tau * acc;
            x[off] = nx;
            if (out_extra) out_extra[off] = nx;
        } else {
            gphi[off] = dotm[off] + acc;
        }
    }
}

// ---------------- row norms + gamma update ----------------
__global__ void k_rownorm(const float* __restrict__ gphi) {
    __shared__ float red[256];
    int bidx = blockIdx.x;
    float s = 0.f;
    for (int j = threadIdx.x; j < NPIX; j += 256) {
        float v = gphi[(size_t)bidx * NPIX + j];
        s = fmaf(v, v, s);
    }
    red[threadIdx.x] = s;
    __syncthreads();
    for (int off = 128; off > 0; off >>= 1) {
        if (threadIdx.x < off) red[threadIdx.x] += red[threadIdx.x + off];
        __syncthreads();
    }
    if (threadIdx.x == 0) d_ngrad[bidx] = sqrtf(red[0]);
}

__global__ void k_gamma(const float* __restrict__ soft_thr) {
    __shared__ float red[256];
    red[threadIdx.x] = d_ngrad[threadIdx.x];
    __syncthreads();
    for (int off = 128; off > 0; off >>= 1) {
        if (threadIdx.x < off) red[threadIdx.x] += red[threadIdx.x + off];
        __syncthreads();
    }
    if (threadIdx.x == 0) {
        float mean = red[0] / (float)BB;
        float g = d_gamma;
        if (mean < 15000.0f * g * soft_thr[0]) g *= 0.9f;
        d_gamma = g;
    }
}

// ---------------- host orchestration ----------------
static void grad_r_chain(const float* src, const float* c1, const float* c2,
                         const float* c3, const float* c4, const float* soft,
                         unsigned int* px1, unsigned int* px2, unsigned int* px3,
                         unsigned int* pg, unsigned int* pbA,
                         const float* pz, float* px, const float* pdotm, float* pgphi,
                         const float* alphas, const float* betas,
                         int phase, int mode, float* out_extra) {
    dim3 g2(BB, 2);
    k_convTC<<<g2, TC_THREADS, SMEM_TCH2>>>(px1, c2, px2, px1, soft, FLAG_CONV1,
                                            src, c1, px1);
    k_convTC<<<g2, TC_THREADS, SMEM_TCH>>>(px2, c3, px3, px1, soft, FLAG_ACT_IN,
                                           nullptr, nullptr, nullptr);
    k_convTC<<<g2, TC_THREADS, SMEM_TCH>>>(px3, c4, pg,  px1, soft, FLAG_ACT_IN,
                                           nullptr, nullptr, nullptr);
    k_convTC<<<g2, TC_THREADS, SMEM_TCH>>>(pg,  c4, pbA, px3, soft,
                                           FLAG_FLIP | FLAG_ACTDER | FLAG_GNORM,
                                           nullptr, nullptr, nullptr);
    k_convTC<<<g2, TC_THREADS, SMEM_TCH>>>(pbA, c3, pg,  px2, soft,
                                           FLAG_FLIP | FLAG_ACTDER,
                                           nullptr, nullptr, nullptr);
    k_convTC<<<g2, TC_THREADS, SMEM_TCH>>>(pg,  c2, pbA, px1, soft,
                                           FLAG_FLIP | FLAG_ACTDER,
                                           nullptr, nullptr, nullptr);
    k_convT1n<<<BB, T1_THREADS, SMEM_T1N>>>(pbA, c1, pz, px, pdotm, pgphi,
                                            alphas, betas, phase, mode, out_extra);
}

extern "C" void kernel_launch(void* const* d_in, const int* in_sizes, int n_in,
                              void* d_out, int out_size) {
    (void)in_sizes; (void)n_in; (void)out_size;
    const float* Phix   = (const float*)d_in[0];
    const float* Phi    = (const float*)d_in[1];
    const float* Qinit  = (const float*)d_in[2];
    const float* soft   = (const float*)d_in[3];
    const float* alphas = (const float*)d_in[4];
    const float* betas  = (const float*)d_in[5];
    const float* c1     = (const float*)d_in[6];
    const float* c2     = (const float*)d_in[7];
    const float* c3     = (const float*)d_in[8];
    const float* c4     = (const float*)d_in[9];
    float* out = (float*)d_out;

    cudaFuncSetAttribute(k_convTC,  cudaFuncAttributeMaxDynamicSharedMemorySize, SMEM_TCH2);
    cudaFuncSetAttribute(k_convT1n, cudaFuncAttributeMaxDynamicSharedMemorySize, SMEM_T1N);

    float *px, *pz, *pgphi, *pdotm, *pPhiTb;
    unsigned int *px1, *px2, *px3, *pg, *pbA;
    cudaGetSymbolAddress((void**)&px,     d_x);
    cudaGetSymbolAddress((void**)&pz,     d_z);
    cudaGetSymbolAddress((void**)&pgphi,  d_gphi);
    cudaGetSymbolAddress((void**)&pdotm,  d_dotm);
    cudaGetSymbolAddress((void**)&px1,    d_x1);
    cudaGetSymbolAddress((void**)&px2,    d_x2);
    cudaGetSymbolAddress((void**)&px3,    d_x3);
    cudaGetSymbolAddress((void**)&pg,     d_g);
    cudaGetSymbolAddress((void**)&pbA,    d_bA);
    cudaGetSymbolAddress((void**)&pPhiTb, d_PhiTb);

    dim3 tb16(16, 16);
    k_phitphi64<<<dim3(18, 18), tb16>>>(Phi);                       // + gamma init
    k_setupF<<<dim3(35, 8, 2), tb16>>>(Phix, Phi, Qinit, pPhiTb, px);

    for (int p = 0; p < 3; p++) {
        if (p == 0)
            k_gemmP<<<dim3(18, 8), tb16>>>(px, pz, alphas, p, 0);
        else
            k_zstep<<<BB, 256>>>(px, pz, alphas, p);
        grad_r_chain(pz, c1, c2, c3, c4, soft, px1, px2, px3, pg, pbA,
                     pz, px, pdotm, pgphi, alphas, betas, p, 0,
                     (p == 2) ? out : nullptr);
        if (p < 2) {
            k_gemmP<<<dim3(18, 8), tb16>>>(px, pdotm, alphas, p, 1);
            grad_r_chain(px, c1, c2, c3, c4, soft, px1, px2, px3, pg, pbA,
                         pz, px, pdotm, pgphi, alphas, betas, p, 1, nullptr);
            k_rownorm<<<BB, 256>>>(pgphi);
            k_gamma<<<1, 256>>>(soft);
        }
    }
}

// round 15
// speedup vs baseline: 1.0617x; 1.0182x over previous
#include <cuda_runtime.h>
#include <cuda_bf16.h>
#include <math.h>
#include <cstdint>

#define BB   256
#define NPIX 1089
#define MDIM 272
#define CC   32

#define FLAG_ACT_IN 1
#define FLAG_FLIP   2
#define FLAG_ACTDER 4
#define FLAG_GNORM  8
#define FLAG_CONV1  16

// tensor-conv geometry (half-image CTAs, 2 CTAs/SM)
#define TC_THREADS 256
#define T1_THREADS 256
#define FRONT   40            /* margin positions before local row 0 */
#define HROWS   800           /* local padded-position slots per half buffer */
#define SROWS   1360          /* full-image buffer (convT1n) */
#define ROWW    20            /* u32 per position (80B stride, conflict-free ldmatrix) */
#define NTILES  69            /* ceil(1089/16) pixel tiles */
#define TSPLIT  35            /* half 0: tiles [0,35), half 1: [35,69) */
#define KSTEPS  18            /* 9 taps * 32 ci / 16 */

#define OFF_ROWS 18560                           /* wfrag: 72*32*8 = 18432 <= 18560 */
#define SMEM_TCH (OFF_ROWS + HROWS * ROWW * 4)   /* 82560 */
#define OFF_SZ   SMEM_TCH
#define OFF_SW1  (OFF_SZ + HROWS * 4)            /* 85760 */
#define SMEM_TCH2 (OFF_SW1 + 9 * CC * 4)         /* 86912 */
#define SMEM_T1N (SROWS * 64)                    /* 87040 */

typedef unsigned long long u64;

// ---------------- device state (static, no allocation) ----------------
__device__ float d_P[NPIX*NPIX];
__device__ float d_PhiTb[BB*NPIX];
__device__ float d_x[BB*NPIX];
__device__ float d_z[BB*NPIX];
__device__ float d_gphi[BB*NPIX];
__device__ float d_dotm[BB*NPIX];
// pixel-major bf16 tensors: [image][pixel][32ch] as 16 u32 per pixel
__device__ unsigned int d_x1[BB*NPIX*16];
__device__ unsigned int d_x2[BB*NPIX*16];
__device__ unsigned int d_x3[BB*NPIX*16];
__device__ unsigned int d_g [BB*NPIX*16];
__device__ unsigned int d_bA[BB*NPIX*16];
__device__ float d_ngrad[BB];
__device__ float d_gamma;

__device__ __forceinline__ uint32_t smem_to_u32(const void* p) {
    uint32_t a;
    asm("{ .reg .u64 t; cvta.to.shared.u64 t, %1; cvt.u32.u64 %0, t; }" : "=r"(a) : "l"(p));
    return a;
}

// ---------------- bf16 pack/unpack ----------------
__device__ __forceinline__ float2 bupk(unsigned int u) {
    __nv_bfloat162 t = *reinterpret_cast<__nv_bfloat162*>(&u);
    return __bfloat1622float2(t);
}
__device__ __forceinline__ unsigned int bpk(float a, float b) {
    __nv_bfloat162 t = __floats2bfloat162_rn(a, b);
    return *reinterpret_cast<unsigned int*>(&t);
}

// ---------------- activation (eq. 33), DELTA = 0.01 ----------------
__device__ __forceinline__ float actf(float v) {
    if (fabsf(v) > 0.01f) return fmaxf(v, 0.0f);
    return fmaf(v*v, 25.0f, fmaf(v, 0.5f, 0.0025f));
}
__device__ __forceinline__ float actdf(float v) {
    if (fabsf(v) > 0.01f) return v > 0.0f ? 1.0f : 0.0f;
    return fmaf(v, 50.0f, 0.5f);
}

// ---------------- GEMM: P = Phi^T Phi ----------------
__global__ void k_phitphi64(const float* __restrict__ Phi) {
    if (blockIdx.x == 0 && blockIdx.y == 0 && threadIdx.x == 0 && threadIdx.y == 0)
        d_gamma = 1.0f;
    __shared__ float As[16][68];
    __shared__ float Bs[16][68];
    int ib = blockIdx.y * 64, jb = blockIdx.x * 64;
    int tx = threadIdx.x, ty = threadIdx.y;
    int t = ty * 16 + tx;
    float acc[4][4];
    #pragma unroll
    for (int r = 0; r < 4; r++)
        #pragma unroll
        for (int c = 0; c < 4; c++) acc[r][c] = 0.f;
    for (int k0 = 0; k0 < MDIM; k0 += 16) {
        #pragma unroll
        for (int q = t; q < 1024; q += 256) {
            int kk = q / 64, r = q % 64;
            As[kk][r] = (ib + r < NPIX) ? Phi[(k0 + kk) * NPIX + ib + r] : 0.f;
            Bs[kk][r] = (jb + r < NPIX) ? Phi[(k0 + kk) * NPIX + jb + r] : 0.f;
        }
        __syncthreads();
        #pragma unroll
        for (int kk = 0; kk < 16; kk++) {
            float4 a4 = *(const float4*)&As[kk][ty * 4];
            float4 b4 = *(const float4*)&Bs[kk][tx * 4];
            float ar[4] = {a4.x, a4.y, a4.z, a4.w};
            float br[4] = {b4.x, b4.y, b4.z, b4.w};
            #pragma unroll
            for (int r = 0; r < 4; r++)
                #pragma unroll
                for (int c = 0; c < 4; c++)
                    acc[r][c] = fmaf(ar[r], br[c], acc[r][c]);
        }
        __syncthreads();
    }
    #pragma unroll
    for (int r = 0; r < 4; r++) {
        int i = ib + ty * 4 + r;
        if (i >= NPIX) continue;
        #pragma unroll
        for (int c = 0; c < 4; c++) {
            int j = jb + tx * 4 + c;
            if (j < NPIX) d_P[i * NPIX + j] = acc[r][c];
        }
    }
}

// ---------------- phase GEMM: 32x64 tiles ----------------
__global__ void k_gemmP(const float* __restrict__ src, float* __restrict__ dst,
                        const float* __restrict__ alphas, int phase, int mode) {
    __shared__ float As[16][36];
    __shared__ float Bs[16][68];
    int bb = blockIdx.y * 32, jb = blockIdx.x * 64;
    int tx = threadIdx.x, ty = threadIdx.y;
    int t = ty * 16 + tx;
    float acc[2][4];
    #pragma unroll
    for (int r = 0; r < 2; r++)
        #pragma unroll
        for (int c = 0; c < 4; c++) acc[r][c] = 0.f;
    for (int k0 = 0; k0 < NPIX; k0 += 16) {
        #pragma unroll
        for (int q = t; q < 512; q += 256) {
            int r = q / 16, kk = q % 16;
            As[kk][r] = (k0 + kk < NPIX) ? src[(bb + r) * NPIX + k0 + kk] : 0.f;
        }
        #pragma unroll
        for (int q = t; q < 1024; q += 256) {
            int kk = q / 64, c = q % 64;
            Bs[kk][c] = (k0 + kk < NPIX && jb + c < NPIX) ? d_P[(k0 + kk) * NPIX + jb + c] : 0.f;
        }
        __syncthreads();
        #pragma unroll
        for (int kk = 0; kk < 16; kk++) {
            float a0 = As[kk][ty * 2], a1 = As[kk][ty * 2 + 1];
            float4 b4 = *(const float4*)&Bs[kk][tx * 4];
            float br[4] = {b4.x, b4.y, b4.z, b4.w};
            #pragma unroll
            for (int c = 0; c < 4; c++) {
                acc[0][c] = fmaf(a0, br[c], acc[0][c]);
                acc[1][c] = fmaf(a1, br[c], acc[1][c]);
            }
        }
        __syncthreads();
    }
    float alpha = fabsf(alphas[phase]);
    #pragma unroll
    for (int r = 0; r < 2; r++) {
        int b = bb + ty * 2 + r;
        #pragma unroll
        for (int c = 0; c < 4; c++) {
            int j = jb + tx * 4 + c;
            if (j < NPIX) {
                float dot = acc[r][c];
                float ptb = d_PhiTb[b * NPIX + j];
                if (mode == 0)
                    dst[b * NPIX + j] = src[b * NPIX + j] + alpha * (ptb - dot);
                else
                    dst[b * NPIX + j] = dot - ptb;
            }
        }
    }
}

__global__ void k_zstep(const float* __restrict__ x, float* __restrict__ z,
                        const float* __restrict__ alphas, int phase) {
    float alpha = fabsf(alphas[phase]);
    size_t base = (size_t)blockIdx.x * NPIX;
    for (int j = threadIdx.x; j < NPIX; j += blockDim.x)
        z[base + j] = x[base + j] - alpha * d_dotm[base + j];
}

__global__ void k_setupF(const float* __restrict__ Phix, const float* __restrict__ Phi,
                         const float* __restrict__ Qinit,
                         float* __restrict__ dPhiTb, float* __restrict__ dx) {
    __shared__ float As[32][33];
    __shared__ float Bs[32][33];
    int tmode = blockIdx.z;
    const float* Bsrc = tmode == 0 ? Phi : Qinit;
    float* dst = tmode == 0 ? dPhiTb : dx;
    int bb = blockIdx.y * 32, jb = blockIdx.x * 32;
    int tx = threadIdx.x, ty = threadIdx.y;
    int t = ty * 16 + tx;
    float acc00 = 0.f, acc01 = 0.f, acc10 = 0.f, acc11 = 0.f;
    for (int k0 = 0; k0 < MDIM; k0 += 32) {
        for (int q = t; q < 1024; q += 256) {
            int kk = q % 32, r = q / 32;
            As[kk][r] = (k0 + kk < MDIM) ? Phix[(bb + r) * MDIM + k0 + kk] : 0.f;
        }
        if (tmode == 0) {
            for (int q = t; q < 1024; q += 256) {
                int kk = q / 32, j = q % 32;
                Bs[kk][j] = (k0 + kk < MDIM && jb + j < NPIX) ? Bsrc[(k0 + kk) * NPIX + jb + j] : 0.f;
            }
        } else {
            for (int q = t; q < 1024; q += 256) {
                int kk = q % 32, j = q / 32;
                Bs[kk][j] = (k0 + kk < MDIM && jb + j < NPIX) ? Bsrc[(jb + j) * MDIM + k0 + kk] : 0.f;
            }
        }
        __syncthreads();
        #pragma unroll
        for (int kk = 0; kk < 32; kk++) {
            float a0 = As[kk][ty*2], a1 = As[kk][ty*2+1];
            float b0 = Bs[kk][tx*2], b1 = Bs[kk][tx*2+1];
            acc00 = fmaf(a0, b0, acc00); acc01 = fmaf(a0, b1, acc01);
            acc10 = fmaf(a1, b0, acc10); acc11 = fmaf(a1, b1, acc11);
        }
        __syncthreads();
    }
    int b0 = bb + ty*2, j0 = jb + tx*2;
    if (j0     < NPIX) dst[(b0  ) * NPIX + j0  ] = acc00;
    if (j0 + 1 < NPIX) dst[(b0  ) * NPIX + j0+1] = acc01;
    if (j0     < NPIX) dst[(b0+1) * NPIX + j0  ] = acc10;
    if (j0 + 1 < NPIX) dst[(b0+1) * NPIX + j0+1] = acc11;
}

// ---------------- tensor conv (32 -> 32) via mma.sync bf16, half-image, 2 CTA/SM ----
// Weights in fragment-major smem u64: wfrag[(s*4+nb)*32 + lane] = (b0, b1).
__global__ __launch_bounds__(TC_THREADS, 2) void k_convTC(
        const unsigned int* __restrict__ in, const float* __restrict__ w,
        unsigned int* __restrict__ out, const unsigned int* __restrict__ pre,
        const float* __restrict__ soft, int flags,
        const float* __restrict__ zin, const float* __restrict__ w1,
        unsigned int* __restrict__ x1out) {
    extern __shared__ char smem[];
    u64* wfrag = (u64*)smem;                                   // [72][32] u64
    unsigned int* srows = (unsigned int*)(smem + OFF_ROWS);    // HROWS x ROWW u32
    uint32_t rows_addr = smem_to_u32(srows);
    const int dlt[9] = {-37,-36,-35,-1,0,1,35,36,37};
    int tid = threadIdx.x;
    int lane = tid & 31, warp = tid >> 5;
    int n = blockIdx.x;
    int h = blockIdx.y;
    int rbase = h * 16;                 // stored-row (y+1) base of local buffer
    int lbase = FRONT - rbase * 36;     // local pos = lbase + (y+1)*36 + (x+1)

    // zero local rows buffer
    uint4 z4 = make_uint4(0, 0, 0, 0);
    for (int i = tid; i < HROWS * 5; i += TC_THREADS) ((uint4*)srows)[i] = z4;

    // stage weights directly into mma-fragment order
    bool flip = (flags & FLAG_FLIP) != 0;
    for (int idx = tid; idx < CC * CC * 9; idx += TC_THREADS) {
        int kx = idx % 3, ky = (idx / 3) % 3;
        int i = (idx / 9) % CC, o = idx / (9 * CC);
        float v = w[idx];
        int eci, eco, ek;
        if (flip) { eci = o; eco = i; ek = (2 - ky) * 3 + (2 - kx); }
        else      { eci = i; eco = o; ek = ky * 3 + kx; }
        int k = ek * 32 + eci;                 // 0..287
        int s = k >> 4, kk = k & 15;
        int j = kk >> 3, c = kk & 7;           // j: which u32 (b0/b1), c: col in 8
        int nb = eco >> 3;
        int flane = ((eco & 7) << 2) | (c >> 1);
        *(__nv_bfloat16*)(smem + (((s * 4 + nb) * 32 + flane) << 3) + (j << 2) + ((c & 1) << 1))
            = __float2bfloat16(v);
    }

    // pixel rows this half must have staged: y in [rbase-1, rbase+18] clamped
    int ylo = rbase - 1; if (ylo < 0) ylo = 0;
    int yhi = rbase + 18; if (yhi > 32) yhi = 32;

    if (flags & FLAG_CONV1) {
        // ---- conv1 fused: z f32 -> x1 (gmem bf16) + act(x1) (rows) ----
        float* s_z  = (float*)(smem + OFF_SZ);
        float* s_w1 = (float*)(smem + OFF_SW1);   // [k][co]
        for (int i = tid; i < HROWS; i += TC_THREADS) s_z[i] = 0.f;
        for (int i = tid; i < 9 * CC; i += TC_THREADS) {
            int o = i / 9, k = i % 9;
            s_w1[k * CC + o] = w1[i];
        }
        __syncthreads();
        const float* zb = zin + (size_t)n * NPIX;
        int zlo = ylo - 1; if (zlo < 0) zlo = 0;
        int zhi = yhi + 1; if (zhi > 32) zhi = 32;
        for (int p = zlo * 33 + tid; p < (zhi + 1) * 33; p += TC_THREADS) {
            int y = p / 33, x = p - y * 33;
            s_z[lbase + (y + 1) * 36 + (x + 1)] = zb[p];
        }
        __syncthreads();
        unsigned int* xo = x1out + (size_t)n * NPIX * 16;
        for (int p = ylo * 33 + tid; p < (yhi + 1) * 33; p += TC_THREADS) {
            int y = p / 33, x = p - y * 33;
            int pp = lbase + (y + 1) * 36 + (x + 1);
            float zv[9];
            #pragma unroll
            for (int k = 0; k < 9; k++) zv[k] = s_z[pp + dlt[k]];
            unsigned int* row = xo + p * 16;
            unsigned int* rw = srows + pp * ROWW;
            #pragma unroll 1
            for (int ch = 0; ch < 4; ch++) {
                float acc[8];
                #pragma unroll
                for (int j = 0; j < 8; j++) acc[j] = 0.f;
                #pragma unroll
                for (int k = 0; k < 9; k++) {
                    float4 w0 = *(const float4*)(s_w1 + k * CC + ch * 8);
                    float4 w1v = *(const float4*)(s_w1 + k * CC + ch * 8 + 4);
                    acc[0] = fmaf(zv[k], w0.x, acc[0]);
                    acc[1] = fmaf(zv[k], w0.y, acc[1]);
                    acc[2] = fmaf(zv[k], w0.z, acc[2]);
                    acc[3] = fmaf(zv[k], w0.w, acc[3]);
                    acc[4] = fmaf(zv[k], w1v.x, acc[4]);
                    acc[5] = fmaf(zv[k], w1v.y, acc[5]);
                    acc[6] = fmaf(zv[k], w1v.z, acc[6]);
                    acc[7] = fmaf(zv[k], w1v.w, acc[7]);
                }
                uint4 xv = make_uint4(bpk(acc[0], acc[1]), bpk(acc[2], acc[3]),
                                      bpk(acc[4], acc[5]), bpk(acc[6], acc[7]));
                *(uint4*)(row + ch * 4) = xv;
                uint4 av = make_uint4(bpk(actf(acc[0]), actf(acc[1])),
                                      bpk(actf(acc[2]), actf(acc[3])),
                                      bpk(actf(acc[4]), actf(acc[5])),
                                      bpk(actf(acc[6]), actf(acc[7])));
                *(uint4*)(rw + ch * 4) = av;
            }
        }
    } else {
        __syncthreads();
        // stage input pixels (fused act / gnorm)
        const uint4* inb = (const uint4*)in + (size_t)n * NPIX * 4;
        bool act_in = (flags & FLAG_ACT_IN) != 0;
        bool gn = (flags & FLAG_GNORM) != 0;
        float thr = 0.f, invthr = 0.f;
        if (gn) { thr = soft[0] * d_gamma; invthr = 1.0f / thr; }
        for (int p = ylo * 33 + tid; p < (yhi + 1) * 33; p += TC_THREADS) {
            int y = p / 33, x = p - y * 33;
            int row = lbase + (y + 1) * 36 + (x + 1);
            uint4 q0 = inb[p*4+0], q1 = inb[p*4+1], q2 = inb[p*4+2], q3 = inb[p*4+3];
            unsigned int u[16] = {q0.x,q0.y,q0.z,q0.w, q1.x,q1.y,q1.z,q1.w,
                                  q2.x,q2.y,q2.z,q2.w, q3.x,q3.y,q3.z,q3.w};
            if (act_in) {
                #pragma unroll
                for (int j = 0; j < 16; j++) {
                    float2 f = bupk(u[j]);
                    u[j] = bpk(actf(f.x), actf(f.y));
                }
            } else if (gn) {
                float2 f[16];
                float s = 0.f;
                #pragma unroll
                for (int j = 0; j < 16; j++) {
                    f[j] = bupk(u[j]);
                    s = fmaf(f[j].x, f[j].x, fmaf(f[j].y, f[j].y, s));
                }
                float nrm = sqrtf(s);
                float fac = (nrm > thr) ? (1.0f / fmaxf(nrm, 1e-12f)) : invthr;
                #pragma unroll
                for (int j = 0; j < 16; j++)
                    u[j] = bpk(f[j].x * fac, f[j].y * fac);
            }
            uint4* dst = (uint4*)(srows + row * ROWW);
            dst[0] = make_uint4(u[0],u[1],u[2],u[3]);
            dst[1] = make_uint4(u[4],u[5],u[6],u[7]);
            dst[2] = make_uint4(u[8],u[9],u[10],u[11]);
            dst[3] = make_uint4(u[12],u[13],u[14],u[15]);
        }
    }
    __syncthreads();

    unsigned int* outp = out + (size_t)n * NPIX * 16;
    const unsigned int* prep = pre + (size_t)n * NPIX * 16;
    bool actder = (flags & FLAG_ACTDER) != 0;

    int tstart = h ? TSPLIT : 0;
    int tend   = h ? NTILES : TSPLIT;
    const u64* wf = wfrag + lane;

    for (int tile = tstart + warp; tile < tend; tile += 8) {
        int p0 = tile * 16;
        int pl = p0 + (lane & 15); if (pl > NPIX - 1) pl = NPIX - 1;
        int y = pl / 33, x = pl - y * 33;
        uint32_t abase = rows_addr
                       + (uint32_t)((lbase + (y + 1) * 36 + (x + 1)) * 80)
                       + (uint32_t)((lane >> 4) * 16);

        float d[4][4];
        #pragma unroll
        for (int nb = 0; nb < 4; nb++)
            #pragma unroll
            for (int j = 0; j < 4; j++) d[nb][j] = 0.f;

        #pragma unroll
        for (int s = 0; s < KSTEPS; s++) {
            int t = s >> 1, hh = s & 1;
            uint32_t aaddr = abase + (uint32_t)(dlt[t] * 80 + hh * 32);
            uint32_t a0, a1, a2, a3;
            asm volatile("ldmatrix.sync.aligned.m8n8.x4.shared.b16 {%0,%1,%2,%3}, [%4];"
                         : "=r"(a0), "=r"(a1), "=r"(a2), "=r"(a3) : "r"(aaddr));
            #pragma unroll
            for (int nb = 0; nb < 4; nb++) {
                u64 wv = wf[(s * 4 + nb) * 32];        // LDS.64, conflict-free
                uint2 wu = *reinterpret_cast<uint2*>(&wv);
                asm volatile(
                    "mma.sync.aligned.m16n8k16.row.col.f32.bf16.bf16.f32 "
                    "{%0,%1,%2,%3}, {%4,%5,%6,%7}, {%8,%9}, {%0,%1,%2,%3};"
                    : "+f"(d[nb][0]), "+f"(d[nb][1]), "+f"(d[nb][2]), "+f"(d[nb][3])
                    : "r"(a0), "r"(a1), "r"(a2), "r"(a3), "r"(wu.x), "r"(wu.y));
            }
        }

        // epilogue: D (16x32 f32) -> pixel-major bf16 u32
        int pA = p0 + (lane >> 2);
        int pB = pA + 8;
        #pragma unroll
        for (int nb = 0; nb < 4; nb++) {
            int ci = nb * 4 + (lane & 3);     // u32 (co-pair) index within pixel
            if (pA < NPIX) {
                float c0 = d[nb][0], c1 = d[nb][1];
                if (actder) {
                    float2 f = bupk(prep[pA * 16 + ci]);
                    c0 *= actdf(f.x); c1 *= actdf(f.y);
                }
                outp[pA * 16 + ci] = bpk(c0, c1);
            }
            if (pB < NPIX) {
                float c2 = d[nb][2], c3 = d[nb][3];
                if (actder) {
                    float2 f = bupk(prep[pB * 16 + ci]);
                    c2 *= actdf(f.x); c3 *= actdf(f.y);
                }
                outp[pB * 16 + ci] = bpk(c2, c3);
            }
        }
    }
}

// ---------------- convT1 (32 -> 1) from bf16 pixel-major, fused update ----------------
__global__ __launch_bounds__(T1_THREADS) void k_convT1n(
        const unsigned int* __restrict__ in, const float* __restrict__ w1,
        const float* __restrict__ z, float* __restrict__ x,
        const float* __restrict__ dotm, float* __restrict__ gphi,
        const float* __restrict__ alphas, const float* __restrict__ betas,
        int phase, int mode, float* __restrict__ out_extra) {
    extern __shared__ char smem[];
    unsigned int* srows = (unsigned int*)smem;     // SROWS * 16 u32
    __shared__ float s_w[CC * 9];                  // flipped [o][k]
    const int dlt[9] = {-37,-36,-35,-1,0,1,35,36,37};
    int n = blockIdx.x, tid = threadIdx.x;

    uint4 z4 = make_uint4(0, 0, 0, 0);
    for (int i = tid; i < SROWS * 4; i += T1_THREADS) ((uint4*)srows)[i] = z4;
    for (int idx = tid; idx < CC * 9; idx += T1_THREADS) {
        int o = idx / 9, k = idx % 9;
        int ky = k / 3, kx = k % 3;
        s_w[o * 9 + (2 - ky) * 3 + (2 - kx)] = w1[idx];
    }
    __syncthreads();
    const uint4* inb = (const uint4*)in + (size_t)n * NPIX * 4;
    for (int p = tid; p < NPIX; p += T1_THREADS) {
        int y = p / 33, xx = p - y * 33;
        int row = FRONT + (y + 1) * 36 + (xx + 1);
        uint4* dst = (uint4*)(srows + row * 16);
        dst[0] = inb[p*4+0]; dst[1] = inb[p*4+1];
        dst[2] = inb[p*4+2]; dst[3] = inb[p*4+3];
    }
    __syncthreads();

    float a = fabsf(alphas[phase]), b = fabsf(betas[phase]);
    float tau = a * b / (a + b);

    for (int p = tid; p < NPIX; p += T1_THREADS) {
        int y = p / 33, xx = p - y * 33;
        int pp = FRONT + (y + 1) * 36 + (xx + 1);
        float acc = 0.f;
        #pragma unroll
        for (int k = 0; k < 9; k++) {
            const uint4* rp = (const uint4*)(srows + (pp + dlt[k]) * 16);
            uint4 r0 = rp[0], r1 = rp[1], r2 = rp[2], r3 = rp[3];
            unsigned int u[16] = {r0.x,r0.y,r0.z,r0.w, r1.x,r1.y,r1.z,r1.w,
                                  r2.x,r2.y,r2.z,r2.w, r3.x,r3.y,r3.z,r3.w};
            #pragma unroll
            for (int j = 0; j < 16; j++) {
                float2 f = bupk(u[j]);
                acc = fmaf(f.x, s_w[(2*j) * 9 + k], acc);
                acc = fmaf(f.y, s_w[(2*j+1) * 9 + k], acc);
            }
        }
        size_t off = (size_t)n * NPIX + p;
        if (mode == 0) {
            float nx = z[off] - tau * acc;
            x[off] = nx;
            if (out_extra) out_extra[off] = nx;
        } else {
            gphi[off] = dotm[off] + acc;
        }
    }
}

// ---------------- row norms + gamma update ----------------
__global__ void k_rownorm(const float* __restrict__ gphi) {
    __shared__ float red[256];
    int bidx = blockIdx.x;
    float s = 0.f;
    for (int j = threadIdx.x; j < NPIX; j += 256) {
        float v = gphi[(size_t)bidx * NPIX + j];
        s = fmaf(v, v, s);
    }
    red[threadIdx.x] = s;
    __syncthreads();
    for (int off = 128; off > 0; off >>= 1) {
        if (threadIdx.x < off) red[threadIdx.x] += red[threadIdx.x + off];
        __syncthreads();
    }
    if (threadIdx.x == 0) d_ngrad[bidx] = sqrtf(red[0]);
}

__global__ void k_gamma(const float* __restrict__ soft_thr) {
    __shared__ float red[256];
    red[threadIdx.x] = d_ngrad[threadIdx.x];
    __syncthreads();
    for (int off = 128; off > 0; off >>= 1) {
        if (threadIdx.x < off) red[threadIdx.x] += red[threadIdx.x + off];
        __syncthreads();
    }
    if (threadIdx.x == 0) {
        float mean = red[0] / (float)BB;
        float g = d_gamma;
        if (mean < 15000.0f * g * soft_thr[0]) g *= 0.9f;
        d_gamma = g;
    }
}

// ---------------- host orchestration ----------------
static void grad_r_chain(const float* src, const float* c1, const float* c2,
                         const float* c3, const float* c4, const float* soft,
                         unsigned int* px1, unsigned int* px2, unsigned int* px3,
                         unsigned int* pg, unsigned int* pbA,
                         const float* pz, float* px, const float* pdotm, float* pgphi,
                         const float* alphas, const float* betas,
                         int phase, int mode, float* out_extra) {
    dim3 g2(BB, 2);
    k_convTC<<<g2, TC_THREADS, SMEM_TCH2>>>(px1, c2, px2, px1, soft, FLAG_CONV1,
                                            src, c1, px1);
    k_convTC<<<g2, TC_THREADS, SMEM_TCH>>>(px2, c3, px3, px1, soft, FLAG_ACT_IN,
                                           nullptr, nullptr, nullptr);
    k_convTC<<<g2, TC_THREADS, SMEM_TCH>>>(px3, c4, pg,  px1, soft, FLAG_ACT_IN,
                                           nullptr, nullptr, nullptr);
    k_convTC<<<g2, TC_THREADS, SMEM_TCH>>>(pg,  c4, pbA, px3, soft,
                                           FLAG_FLIP | FLAG_ACTDER | FLAG_GNORM,
                                           nullptr, nullptr, nullptr);
    k_convTC<<<g2, TC_THREADS, SMEM_TCH>>>(pbA, c3, pg,  px2, soft,
                                           FLAG_FLIP | FLAG_ACTDER,
                                           nullptr, nullptr, nullptr);
    k_convTC<<<g2, TC_THREADS, SMEM_TCH>>>(pg,  c2, pbA, px1, soft,
                                           FLAG_FLIP | FLAG_ACTDER,
                                           nullptr, nullptr, nullptr);
    k_convT1n<<<BB, T1_THREADS, SMEM_T1N>>>(pbA, c1, pz, px, pdotm, pgphi,
                                            alphas, betas, phase, mode, out_extra);
}

extern "C" void kernel_launch(void* const* d_in, const int* in_sizes, int n_in,
                              void* d_out, int out_size) {
    (void)in_sizes; (void)n_in; (void)out_size;
    const float* Phix   = (const float*)d_in[0];
    const float* Phi    = (const float*)d_in[1];
    const float* Qinit  = (const float*)d_in[2];
    const float* soft   = (const float*)d_in[3];
    const float* alphas = (const float*)d_in[4];
    const float* betas  = (const float*)d_in[5];
    const float* c1     = (const float*)d_in[6];
    const float* c2     = (const float*)d_in[7];
    const float* c3     = (const float*)d_in[8];
    const float* c4     = (const float*)d_in[9];
    float* out = (float*)d_out;

    cudaFuncSetAttribute(k_convTC,  cudaFuncAttributeMaxDynamicSharedMemorySize, SMEM_TCH2);
    cudaFuncSetAttribute(k_convT1n, cudaFuncAttributeMaxDynamicSharedMemorySize, SMEM_T1N);

    float *px, *pz, *pgphi, *pdotm, *pPhiTb;
    unsigned int *px1, *px2, *px3, *pg, *pbA;
    cudaGetSymbolAddress((void**)&px,     d_x);
    cudaGetSymbolAddress((void**)&pz,     d_z);
    cudaGetSymbolAddress((void**)&pgphi,  d_gphi);
    cudaGetSymbolAddress((void**)&pdotm,  d_dotm);
    cudaGetSymbolAddress((void**)&px1,    d_x1);
    cudaGetSymbolAddress((void**)&px2,    d_x2);
    cudaGetSymbolAddress((void**)&px3,    d_x3);
    cudaGetSymbolAddress((void**)&pg,     d_g);
    cudaGetSymbolAddress((void**)&pbA,    d_bA);
    cudaGetSymbolAddress((void**)&pPhiTb, d_PhiTb);

    dim3 tb16(16, 16);
    k_phitphi64<<<dim3(18, 18), tb16>>>(Phi);                       // + gamma init
    k_setupF<<<dim3(35, 8, 2), tb16>>>(Phix, Phi, Qinit, pPhiTb, px);

    for (int p = 0; p < 3; p++) {
        if (p == 0)
            k_gemmP<<<dim3(18, 8), tb16>>>(px, pz, alphas, p, 0);
        else
            k_zstep<<<BB, 256>>>(px, pz, alphas, p);
        grad_r_chain(pz, c1, c2, c3, c4, soft, px1, px2, px3, pg, pbA,
                     pz, px, pdotm, pgphi, alphas, betas, p, 0,
                     (p == 2) ? out : nullptr);
        if (p < 2) {
            k_gemmP<<<dim3(18, 8), tb16>>>(px, pdotm, alphas, p, 1);
            grad_r_chain(px, c1, c2, c3, c4, soft, px1, px2, px3, pg, pbA,
                         pz, px, pdotm, pgphi, alphas, betas, p, 1, nullptr);
            k_rownorm<<<BB, 256>>>(pgphi);
            k_gamma<<<1, 256>>>(soft);
        }
    }
}

// round 16
// speedup vs baseline: 1.2159x; 1.1452x over previous
#include <cuda_runtime.h>
#include <cuda_bf16.h>
#include <math.h>
#include <cstdint>

#define BB   256
#define NPIX 1089
#define MDIM 272
#define CC   32

#define FLAG_ACT_IN 1
#define FLAG_FLIP   2
#define FLAG_ACTDER 4
#define FLAG_GNORM  8
#define FLAG_CONV1  16

// tensor-conv geometry
#define TC_THREADS 256
#define T1_THREADS 256
#define FRONT   40            /* zero rows before padded-pixel 0 */
#define SROWS   1360
#define ROWW    20            /* u32 per smem row (80B stride, conflict-free ldmatrix) */
#define NTILES  69            /* ceil(1089/16) pixel tiles */
#define KSTEPS  18            /* 9 taps * 32 ci / 16 */
#define WT_STRIDE 290         /* bf16 per Wt row (32 co rows) */
#define NHALO   171           /* halo slots: row0(36) + rows1-33 cols{0,34,35}(99) + row34(36) */

#define OFF_ROWS (CC * WT_STRIDE * 2)            /* 18560 */
#define SMEM_TC  (OFF_ROWS + SROWS * ROWW * 4)   /* 127360 */
#define OFF_SZ   SMEM_TC
#define OFF_SW1  (OFF_SZ + SROWS * 4)            /* 132800 */
#define SMEM_TC2 (OFF_SW1 + 9 * CC * 4)          /* 133952 */
#define SMEM_T1N (SROWS * 64)                    /* 87040 */

// halo slot index (0..170) -> padded-position offset (relative to FRONT)
__device__ __forceinline__ int halo_slot(int idx) {
    if (idx < 36) return idx;                               // row 0
    if (idx < 135) {
        int r = (idx - 36) / 3 + 1, c3 = (idx - 36) % 3;    // rows 1..33, cols 0/34/35
        return r * 36 + (c3 == 0 ? 0 : 33 + c3);
    }
    return 1224 + (idx - 135);                              // row 34 (+ slot 1259 pad)
}

// ---------------- device state (static, no allocation) ----------------
__device__ float d_P[NPIX*NPIX];
__device__ float d_PhiTb[BB*NPIX];
__device__ float d_x[BB*NPIX];
__device__ float d_z[BB*NPIX];
__device__ float d_gphi[BB*NPIX];
__device__ float d_dotm[BB*NPIX];
// pixel-major bf16 tensors: [image][pixel][32ch] as 16 u32 per pixel
__device__ unsigned int d_x1[BB*NPIX*16];
__device__ unsigned int d_x2[BB*NPIX*16];
__device__ unsigned int d_x3[BB*NPIX*16];
__device__ unsigned int d_g [BB*NPIX*16];
__device__ unsigned int d_bA[BB*NPIX*16];
__device__ float d_ngrad[BB];
__device__ float d_gamma;

__device__ __forceinline__ uint32_t smem_to_u32(const void* p) {
    uint32_t a;
    asm("{ .reg .u64 t; cvta.to.shared.u64 t, %1; cvt.u32.u64 %0, t; }" : "=r"(a) : "l"(p));
    return a;
}

// ---------------- bf16 pack/unpack ----------------
__device__ __forceinline__ float2 bupk(unsigned int u) {
    __nv_bfloat162 t = *reinterpret_cast<__nv_bfloat162*>(&u);
    return __bfloat1622float2(t);
}
__device__ __forceinline__ unsigned int bpk(float a, float b) {
    __nv_bfloat162 t = __floats2bfloat162_rn(a, b);
    return *reinterpret_cast<unsigned int*>(&t);
}

// ---------------- activation (eq. 33), DELTA = 0.01 ----------------
__device__ __forceinline__ float actf(float v) {
    if (fabsf(v) > 0.01f) return fmaxf(v, 0.0f);
    return fmaf(v*v, 25.0f, fmaf(v, 0.5f, 0.0025f));
}
__device__ __forceinline__ float actdf(float v) {
    if (fabsf(v) > 0.01f) return v > 0.0f ? 1.0f : 0.0f;
    return fmaf(v, 50.0f, 0.5f);
}

// ---------------- GEMM: P = Phi^T Phi ----------------
__global__ void k_phitphi64(const float* __restrict__ Phi) {
    if (blockIdx.x == 0 && blockIdx.y == 0 && threadIdx.x == 0 && threadIdx.y == 0)
        d_gamma = 1.0f;
    __shared__ float As[16][68];
    __shared__ float Bs[16][68];
    int ib = blockIdx.y * 64, jb = blockIdx.x * 64;
    int tx = threadIdx.x, ty = threadIdx.y;
    int t = ty * 16 + tx;
    float acc[4][4];
    #pragma unroll
    for (int r = 0; r < 4; r++)
        #pragma unroll
        for (int c = 0; c < 4; c++) acc[r][c] = 0.f;
    for (int k0 = 0; k0 < MDIM; k0 += 16) {
        #pragma unroll
        for (int q = t; q < 1024; q += 256) {
            int kk = q / 64, r = q % 64;
            As[kk][r] = (ib + r < NPIX) ? Phi[(k0 + kk) * NPIX + ib + r] : 0.f;
            Bs[kk][r] = (jb + r < NPIX) ? Phi[(k0 + kk) * NPIX + jb + r] : 0.f;
        }
        __syncthreads();
        #pragma unroll
        for (int kk = 0; kk < 16; kk++) {
            float4 a4 = *(const float4*)&As[kk][ty * 4];
            float4 b4 = *(const float4*)&Bs[kk][tx * 4];
            float ar[4] = {a4.x, a4.y, a4.z, a4.w};
            float br[4] = {b4.x, b4.y, b4.z, b4.w};
            #pragma unroll
            for (int r = 0; r < 4; r++)
                #pragma unroll
                for (int c = 0; c < 4; c++)
                    acc[r][c] = fmaf(ar[r], br[c], acc[r][c]);
        }
        __syncthreads();
    }
    #pragma unroll
    for (int r = 0; r < 4; r++) {
        int i = ib + ty * 4 + r;
        if (i >= NPIX) continue;
        #pragma unroll
        for (int c = 0; c < 4; c++) {
            int j = jb + tx * 4 + c;
            if (j < NPIX) d_P[i * NPIX + j] = acc[r][c];
        }
    }
}

// ---------------- phase GEMM: 32x64 tiles ----------------
__global__ void k_gemmP(const float* __restrict__ src, float* __restrict__ dst,
                        const float* __restrict__ alphas, int phase, int mode) {
    __shared__ float As[16][36];
    __shared__ float Bs[16][68];
    int bb = blockIdx.y * 32, jb = blockIdx.x * 64;
    int tx = threadIdx.x, ty = threadIdx.y;
    int t = ty * 16 + tx;
    float acc[2][4];
    #pragma unroll
    for (int r = 0; r < 2; r++)
        #pragma unroll
        for (int c = 0; c < 4; c++) acc[r][c] = 0.f;
    for (int k0 = 0; k0 < NPIX; k0 += 16) {
        #pragma unroll
        for (int q = t; q < 512; q += 256) {
            int r = q / 16, kk = q % 16;
            As[kk][r] = (k0 + kk < NPIX) ? src[(bb + r) * NPIX + k0 + kk] : 0.f;
        }
        #pragma unroll
        for (int q = t; q < 1024; q += 256) {
            int kk = q / 64, c = q % 64;
            Bs[kk][c] = (k0 + kk < NPIX && jb + c < NPIX) ? d_P[(k0 + kk) * NPIX + jb + c] : 0.f;
        }
        __syncthreads();
        #pragma unroll
        for (int kk = 0; kk < 16; kk++) {
            float a0 = As[kk][ty * 2], a1 = As[kk][ty * 2 + 1];
            float4 b4 = *(const float4*)&Bs[kk][tx * 4];
            float br[4] = {b4.x, b4.y, b4.z, b4.w};
            #pragma unroll
            for (int c = 0; c < 4; c++) {
                acc[0][c] = fmaf(a0, br[c], acc[0][c]);
                acc[1][c] = fmaf(a1, br[c], acc[1][c]);
            }
        }
        __syncthreads();
    }
    float alpha = fabsf(alphas[phase]);
    #pragma unroll
    for (int r = 0; r < 2; r++) {
        int b = bb + ty * 2 + r;
        #pragma unroll
        for (int c = 0; c < 4; c++) {
            int j = jb + tx * 4 + c;
            if (j < NPIX) {
                float dot = acc[r][c];
                float ptb = d_PhiTb[b * NPIX + j];
                if (mode == 0)
                    dst[b * NPIX + j] = src[b * NPIX + j] + alpha * (ptb - dot);
                else
                    dst[b * NPIX + j] = dot - ptb;
            }
        }
    }
}

__global__ void k_zstep(const float* __restrict__ x, float* __restrict__ z,
                        const float* __restrict__ alphas, int phase) {
    float alpha = fabsf(alphas[phase]);
    size_t base = (size_t)blockIdx.x * NPIX;
    for (int j = threadIdx.x; j < NPIX; j += blockDim.x)
        z[base + j] = x[base + j] - alpha * d_dotm[base + j];
}

__global__ void k_setupF(const float* __restrict__ Phix, const float* __restrict__ Phi,
                         const float* __restrict__ Qinit,
                         float* __restrict__ dPhiTb, float* __restrict__ dx) {
    __shared__ float As[32][33];
    __shared__ float Bs[32][33];
    int tmode = blockIdx.z;
    const float* Bsrc = tmode == 0 ? Phi : Qinit;
    float* dst = tmode == 0 ? dPhiTb : dx;
    int bb = blockIdx.y * 32, jb = blockIdx.x * 32;
    int tx = threadIdx.x, ty = threadIdx.y;
    int t = ty * 16 + tx;
    float acc00 = 0.f, acc01 = 0.f, acc10 = 0.f, acc11 = 0.f;
    for (int k0 = 0; k0 < MDIM; k0 += 32) {
        for (int q = t; q < 1024; q += 256) {
            int kk = q % 32, r = q / 32;
            As[kk][r] = (k0 + kk < MDIM) ? Phix[(bb + r) * MDIM + k0 + kk] : 0.f;
        }
        if (tmode == 0) {
            for (int q = t; q < 1024; q += 256) {
                int kk = q / 32, j = q % 32;
                Bs[kk][j] = (k0 + kk < MDIM && jb + j < NPIX) ? Bsrc[(k0 + kk) * NPIX + jb + j] : 0.f;
            }
        } else {
            for (int q = t; q < 1024; q += 256) {
                int kk = q % 32, j = q / 32;
                Bs[kk][j] = (k0 + kk < MDIM && jb + j < NPIX) ? Bsrc[(jb + j) * MDIM + k0 + kk] : 0.f;
            }
        }
        __syncthreads();
        #pragma unroll
        for (int kk = 0; kk < 32; kk++) {
            float a0 = As[kk][ty*2], a1 = As[kk][ty*2+1];
            float b0 = Bs[kk][tx*2], b1 = Bs[kk][tx*2+1];
            acc00 = fmaf(a0, b0, acc00); acc01 = fmaf(a0, b1, acc01);
            acc10 = fmaf(a1, b0, acc10); acc11 = fmaf(a1, b1, acc11);
        }
        __syncthreads();
    }
    int b0 = bb + ty*2, j0 = jb + tx*2;
    if (j0     < NPIX) dst[(b0  ) * NPIX + j0  ] = acc00;
    if (j0 + 1 < NPIX) dst[(b0  ) * NPIX + j0+1] = acc01;
    if (j0     < NPIX) dst[(b0+1) * NPIX + j0  ] = acc10;
    if (j0 + 1 < NPIX) dst[(b0+1) * NPIX + j0+1] = acc11;
}

// ---------------- tensor conv (32 -> 32) via mma.sync bf16, B in registers ---------
// FLAG_CONV1: input is z (f32); conv1 computed inline, x1 -> gmem, act(x1) -> rows.
__global__ __launch_bounds__(TC_THREADS) void k_convTC(
        const unsigned int* __restrict__ in, const float* __restrict__ w,
        unsigned int* __restrict__ out, const unsigned int* __restrict__ pre,
        const float* __restrict__ soft, int flags,
        const float* __restrict__ zin, const float* __restrict__ w1,
        unsigned int* __restrict__ x1out) {
    extern __shared__ char smem[];
    __nv_bfloat16* wt = (__nv_bfloat16*)smem;                 // [32][WT_STRIDE]
    unsigned int* srows = (unsigned int*)(smem + OFF_ROWS);   // SROWS x ROWW u32
    uint32_t rows_addr = smem_to_u32(srows);
    const int dlt[9] = {-37,-36,-35,-1,0,1,35,36,37};
    int tid = threadIdx.x;
    int lane = tid & 31, warp = tid >> 5;
    int n = blockIdx.x;

    // zero only the halo positions (staged data overwrites everything else)
    uint4 z4 = make_uint4(0, 0, 0, 0);
    for (int i = tid; i < NHALO * 5; i += TC_THREADS) {
        int idx = i / 5, q = i % 5;
        ((uint4*)(srows + (FRONT + halo_slot(idx)) * ROWW))[q] = z4;
    }

    // stage weights transposed: Wt[co][tap*32+ci]
    bool flip = (flags & FLAG_FLIP) != 0;
    for (int idx = tid; idx < CC * CC * 9; idx += TC_THREADS) {
        int kx = idx % 3, ky = (idx / 3) % 3;
        int i = (idx / 9) % CC, o = idx / (9 * CC);
        float v = w[idx];
        int eci, eco, ek;
        if (flip) { eci = o; eco = i; ek = (2 - ky) * 3 + (2 - kx); }
        else      { eci = i; eco = o; ek = ky * 3 + kx; }
        wt[eco * WT_STRIDE + ek * 32 + eci] = __float2bfloat16(v);
    }

    if (flags & FLAG_CONV1) {
        // ---- conv1 fused: z f32 -> x1 (gmem bf16) + act(x1) (rows) ----
        float* s_z  = (float*)(smem + OFF_SZ);
        float* s_w1 = (float*)(smem + OFF_SW1);   // [k][co]
        for (int i = tid; i < NHALO; i += TC_THREADS)
            s_z[FRONT + halo_slot(i)] = 0.f;
        for (int i = tid; i < 9 * CC; i += TC_THREADS) {
            int o = i / 9, k = i % 9;
            s_w1[k * CC + o] = w1[i];
        }
        const float* zb = zin + (size_t)n * NPIX;
        for (int p = tid; p < NPIX; p += TC_THREADS) {
            int y = p / 33, x = p - y * 33;
            s_z[FRONT + (y + 1) * 36 + (x + 1)] = zb[p];
        }
        __syncthreads();
        unsigned int* xo = x1out + (size_t)n * NPIX * 16;
        for (int p = tid; p < NPIX; p += TC_THREADS) {
            int y = p / 33, x = p - y * 33;
            int pp = FRONT + (y + 1) * 36 + (x + 1);
            float zv[9];
            #pragma unroll
            for (int k = 0; k < 9; k++) zv[k] = s_z[pp + dlt[k]];
            unsigned int* row = xo + p * 16;
            unsigned int* rw = srows + pp * ROWW;
            #pragma unroll 1
            for (int ch = 0; ch < 4; ch++) {
                float acc[8];
                #pragma unroll
                for (int j = 0; j < 8; j++) acc[j] = 0.f;
                #pragma unroll
                for (int k = 0; k < 9; k++) {
                    float4 w0 = *(const float4*)(s_w1 + k * CC + ch * 8);
                    float4 w1v = *(const float4*)(s_w1 + k * CC + ch * 8 + 4);
                    acc[0] = fmaf(zv[k], w0.x, acc[0]);
                    acc[1] = fmaf(zv[k], w0.y, acc[1]);
                    acc[2] = fmaf(zv[k], w0.z, acc[2]);
                    acc[3] = fmaf(zv[k], w0.w, acc[3]);
                    acc[4] = fmaf(zv[k], w1v.x, acc[4]);
                    acc[5] = fmaf(zv[k], w1v.y, acc[5]);
                    acc[6] = fmaf(zv[k], w1v.z, acc[6]);
                    acc[7] = fmaf(zv[k], w1v.w, acc[7]);
                }
                uint4 xv = make_uint4(bpk(acc[0], acc[1]), bpk(acc[2], acc[3]),
                                      bpk(acc[4], acc[5]), bpk(acc[6], acc[7]));
                *(uint4*)(row + ch * 4) = xv;
                uint4 av = make_uint4(bpk(actf(acc[0]), actf(acc[1])),
                                      bpk(actf(acc[2]), actf(acc[3])),
                                      bpk(actf(acc[4]), actf(acc[5])),
                                      bpk(actf(acc[6]), actf(acc[7])));
                *(uint4*)(rw + ch * 4) = av;
            }
        }
    } else {
        // stage input pixels (fused act / gnorm); disjoint from halo zeroing
        const uint4* inb = (const uint4*)in + (size_t)n * NPIX * 4;
        bool act_in = (flags & FLAG_ACT_IN) != 0;
        bool gn = (flags & FLAG_GNORM) != 0;
        float thr = 0.f, invthr = 0.f;
        if (gn) { thr = soft[0] * d_gamma; invthr = 1.0f / thr; }
        for (int p = tid; p < NPIX; p += TC_THREADS) {
            int y = p / 33, x = p - y * 33;
            int row = FRONT + (y + 1) * 36 + (x + 1);
            uint4 q0 = inb[p*4+0], q1 = inb[p*4+1], q2 = inb[p*4+2], q3 = inb[p*4+3];
            unsigned int u[16] = {q0.x,q0.y,q0.z,q0.w, q1.x,q1.y,q1.z,q1.w,
                                  q2.x,q2.y,q2.z,q2.w, q3.x,q3.y,q3.z,q3.w};
            if (act_in) {
                #pragma unroll
                for (int j = 0; j < 16; j++) {
                    float2 f = bupk(u[j]);
                    u[j] = bpk(actf(f.x), actf(f.y));
                }
            } else if (gn) {
                float2 f[16];
                float s = 0.f;
                #pragma unroll
                for (int j = 0; j < 16; j++) {
                    f[j] = bupk(u[j]);
                    s = fmaf(f[j].x, f[j].x, fmaf(f[j].y, f[j].y, s));
                }
                float nrm = sqrtf(s);
                float fac = (nrm > thr) ? (1.0f / fmaxf(nrm, 1e-12f)) : invthr;
                #pragma unroll
                for (int j = 0; j < 16; j++)
                    u[j] = bpk(f[j].x * fac, f[j].y * fac);
            }
            uint4* dst = (uint4*)(srows + row * ROWW);
            dst[0] = make_uint4(u[0],u[1],u[2],u[3]);
            dst[1] = make_uint4(u[4],u[5],u[6],u[7]);
            dst[2] = make_uint4(u[8],u[9],u[10],u[11]);
            dst[3] = make_uint4(u[12],u[13],u[14],u[15]);
        }
    }
    __syncthreads();

    // preload ALL B fragments into registers (tile-invariant)
    uint32_t breg[KSTEPS][4][2];
    {
        int brow = lane >> 2, bcol = (lane & 3) * 2;
        #pragma unroll
        for (int s = 0; s < KSTEPS; s++) {
            #pragma unroll
            for (int nb = 0; nb < 4; nb++) {
                const __nv_bfloat16* wr = wt + (nb * 8 + brow) * WT_STRIDE + s * 16 + bcol;
                breg[s][nb][0] = *(const uint32_t*)wr;
                breg[s][nb][1] = *(const uint32_t*)(wr + 8);
            }
        }
    }

    unsigned int* outp = out + (size_t)n * NPIX * 16;
    const unsigned int* prep = pre + (size_t)n * NPIX * 16;
    bool actder = (flags & FLAG_ACTDER) != 0;

    for (int tile = warp; tile < NTILES; tile += 8) {
        int p0 = tile * 16;
        int pl = p0 + (lane & 15); if (pl > NPIX - 1) pl = NPIX - 1;
        int y = pl / 33, x = pl - y * 33;
        uint32_t abase = rows_addr
                       + (uint32_t)((FRONT + (y + 1) * 36 + (x + 1)) * 80)
                       + (uint32_t)((lane >> 4) * 16);

        float d[4][4];
        #pragma unroll
        for (int nb = 0; nb < 4; nb++)
            #pragma unroll
            for (int j = 0; j < 4; j++) d[nb][j] = 0.f;

        #pragma unroll
        for (int s = 0; s < KSTEPS; s++) {
            int t = s >> 1, h = s & 1;
            uint32_t aaddr = abase + (uint32_t)(dlt[t] * 80 + h * 32);
            uint32_t a0, a1, a2, a3;
            asm volatile("ldmatrix.sync.aligned.m8n8.x4.shared.b16 {%0,%1,%2,%3}, [%4];"
                         : "=r"(a0), "=r"(a1), "=r"(a2), "=r"(a3) : "r"(aaddr));
            #pragma unroll
            for (int nb = 0; nb < 4; nb++) {
                asm volatile(
                    "mma.sync.aligned.m16n8k16.row.col.f32.bf16.bf16.f32 "
                    "{%0,%1,%2,%3}, {%4,%5,%6,%7}, {%8,%9}, {%0,%1,%2,%3};"
                    : "+f"(d[nb][0]), "+f"(d[nb][1]), "+f"(d[nb][2]), "+f"(d[nb][3])
                    : "r"(a0), "r"(a1), "r"(a2), "r"(a3),
                      "r"(breg[s][nb][0]), "r"(breg[s][nb][1]));
            }
        }

        // epilogue: D (16x32 f32) -> pixel-major bf16 u32
        int pA = p0 + (lane >> 2);
        int pB = pA + 8;
        #pragma unroll
        for (int nb = 0; nb < 4; nb++) {
            int ci = nb * 4 + (lane & 3);     // u32 (co-pair) index within pixel
            if (pA < NPIX) {
                float c0 = d[nb][0], c1 = d[nb][1];
                if (actder) {
                    float2 f = bupk(prep[pA * 16 + ci]);
                    c0 *= actdf(f.x); c1 *= actdf(f.y);
                }
                outp[pA * 16 + ci] = bpk(c0, c1);
            }
            if (pB < NPIX) {
                float c2 = d[nb][2], c3 = d[nb][3];
                if (actder) {
                    float2 f = bupk(prep[pB * 16 + ci]);
                    c2 *= actdf(f.x); c3 *= actdf(f.y);
                }
                outp[pB * 16 + ci] = bpk(c2, c3);
            }
        }
    }
}

// ---------------- convT1 (32 -> 1) from bf16 pixel-major, fused update ----------------
__global__ __launch_bounds__(T1_THREADS) void k_convT1n(
        const unsigned int* __restrict__ in, const float* __restrict__ w1,
        const float* __restrict__ z, float* __restrict__ x,
        const float* __restrict__ dotm, float* __restrict__ gphi,
        const float* __restrict__ alphas, const float* __restrict__ betas,
        int phase, int mode, float* __restrict__ out_extra) {
    extern __shared__ char smem[];
    unsigned int* srows = (unsigned int*)smem;     // SROWS * 16 u32
    __shared__ float s_w[CC * 9];                  // flipped [o][k]
    const int dlt[9] = {-37,-36,-35,-1,0,1,35,36,37};
    int n = blockIdx.x, tid = threadIdx.x;

    // zero only halo positions
    uint4 z4 = make_uint4(0, 0, 0, 0);
    for (int i = tid; i < NHALO * 4; i += T1_THREADS) {
        int idx = i / 4, q = i % 4;
        ((uint4*)(srows + (FRONT + halo_slot(idx)) * 16))[q] = z4;
    }
    for (int idx = tid; idx < CC * 9; idx += T1_THREADS) {
        int o = idx / 9, k = idx % 9;
        int ky = k / 3, kx = k % 3;
        s_w[o * 9 + (2 - ky) * 3 + (2 - kx)] = w1[idx];
    }
    const uint4* inb = (const uint4*)in + (size_t)n * NPIX * 4;
    for (int p = tid; p < NPIX; p += T1_THREADS) {
        int y = p / 33, xx = p - y * 33;
        int row = FRONT + (y + 1) * 36 + (xx + 1);
        uint4* dst = (uint4*)(srows + row * 16);
        dst[0] = inb[p*4+0]; dst[1] = inb[p*4+1];
        dst[2] = inb[p*4+2]; dst[3] = inb[p*4+3];
    }
    __syncthreads();

    float a = fabsf(alphas[phase]), b = fabsf(betas[phase]);
    float tau = a * b / (a + b);

    for (int p = tid; p < NPIX; p += T1_THREADS) {
        int y = p / 33, xx = p - y * 33;
        int pp = FRONT + (y + 1) * 36 + (xx + 1);
        float acc = 0.f;
        #pragma unroll
        for (int k = 0; k < 9; k++) {
            const uint4* rp = (const uint4*)(srows + (pp + dlt[k]) * 16);
            uint4 r0 = rp[0], r1 = rp[1], r2 = rp[2], r3 = rp[3];
            unsigned int u[16] = {r0.x,r0.y,r0.z,r0.w, r1.x,r1.y,r1.z,r1.w,
                                  r2.x,r2.y,r2.z,r2.w, r3.x,r3.y,r3.z,r3.w};
            #pragma unroll
            for (int j = 0; j < 16; j++) {
                float2 f = bupk(u[j]);
                acc = fmaf(f.x, s_w[(2*j) * 9 + k], acc);
                acc = fmaf(f.y, s_w[(2*j+1) * 9 + k], acc);
            }
        }
        size_t off = (size_t)n * NPIX + p;
        if (mode == 0) {
            float nx = z[off] - tau * acc;
            x[off] = nx;
            if (out_extra) out_extra[off] = nx;
        } else {
            gphi[off] = dotm[off] + acc;
        }
    }
}

// ---------------- row norms + gamma update ----------------
__global__ void k_rownorm(const float* __restrict__ gphi) {
    __shared__ float red[256];
    int bidx = blockIdx.x;
    float s = 0.f;
    for (int j = threadIdx.x; j < NPIX; j += 256) {
        float v = gphi[(size_t)bidx * NPIX + j];
        s = fmaf(v, v, s);
    }
    red[threadIdx.x] = s;
    __syncthreads();
    for (int off = 128; off > 0; off >>= 1) {
        if (threadIdx.x < off) red[threadIdx.x] += red[threadIdx.x + off];
        __syncthreads();
    }
    if (threadIdx.x == 0) d_ngrad[bidx] = sqrtf(red[0]);
}

__global__ void k_gamma(const float* __restrict__ soft_thr) {
    __shared__ float red[256];
    red[threadIdx.x] = d_ngrad[threadIdx.x];
    __syncthreads();
    for (int off = 128; off > 0; off >>= 1) {
        if (threadIdx.x < off) red[threadIdx.x] += red[threadIdx.x + off];
        __syncthreads();
    }
    if (threadIdx.x == 0) {
        float mean = red[0] / (float)BB;
        float g = d_gamma;
        if (mean < 15000.0f * g * soft_thr[0]) g *= 0.9f;
        d_gamma = g;
    }
}

// ---------------- host orchestration ----------------
static void grad_r_chain(const float* src, const float* c1, const float* c2,
                         const float* c3, const float* c4, const float* soft,
                         unsigned int* px1, unsigned int* px2, unsigned int* px3,
                         unsigned int* pg, unsigned int* pbA,
                         const float* pz, float* px, const float* pdotm, float* pgphi,
                         const float* alphas, const float* betas,
                         int phase, int mode, float* out_extra) {
    k_convTC<<<BB, TC_THREADS, SMEM_TC2>>>(px1, c2, px2, px1, soft, FLAG_CONV1,
                                           src, c1, px1);
    k_convTC<<<BB, TC_THREADS, SMEM_TC>>>(px2, c3, px3, px1, soft, FLAG_ACT_IN,
                                          nullptr, nullptr, nullptr);
    k_convTC<<<BB, TC_THREADS, SMEM_TC>>>(px3, c4, pg,  px1, soft, FLAG_ACT_IN,
                                          nullptr, nullptr, nullptr);
    k_convTC<<<BB, TC_THREADS, SMEM_TC>>>(pg,  c4, pbA, px3, soft,
                                          FLAG_FLIP | FLAG_ACTDER | FLAG_GNORM,
                                          nullptr, nullptr, nullptr);
    k_convTC<<<BB, TC_THREADS, SMEM_TC>>>(pbA, c3, pg,  px2, soft,
                                          FLAG_FLIP | FLAG_ACTDER,
                                          nullptr, nullptr, nullptr);
    k_convTC<<<BB, TC_THREADS, SMEM_TC>>>(pg,  c2, pbA, px1, soft,
                                          FLAG_FLIP | FLAG_ACTDER,
                                          nullptr, nullptr, nullptr);
    k_convT1n<<<BB, T1_THREADS, SMEM_T1N>>>(pbA, c1, pz, px, pdotm, pgphi,
                                            alphas, betas, phase, mode, out_extra);
}

extern "C" void kernel_launch(void* const* d_in, const int* in_sizes, int n_in,
                              void* d_out, int out_size) {
    (void)in_sizes; (void)n_in; (void)out_size;
    const float* Phix   = (const float*)d_in[0];
    const float* Phi    = (const float*)d_in[1];
    const float* Qinit  = (const float*)d_in[2];
    const float* soft   = (const float*)d_in[3];
    const float* alphas = (const float*)d_in[4];
    const float* betas  = (const float*)d_in[5];
    const float* c1     = (const float*)d_in[6];
    const float* c2     = (const float*)d_in[7];
    const float* c3     = (const float*)d_in[8];
    const float* c4     = (const float*)d_in[9];
    float* out = (float*)d_out;

    cudaFuncSetAttribute(k_convTC,  cudaFuncAttributeMaxDynamicSharedMemorySize, SMEM_TC2);
    cudaFuncSetAttribute(k_convT1n, cudaFuncAttributeMaxDynamicSharedMemorySize, SMEM_T1N);

    float *px, *pz, *pgphi, *pdotm, *pPhiTb;
    unsigned int *px1, *px2, *px3, *pg, *pbA;
    cudaGetSymbolAddress((void**)&px,     d_x);
    cudaGetSymbolAddress((void**)&pz,     d_z);
    cudaGetSymbolAddress((void**)&pgphi,  d_gphi);
    cudaGetSymbolAddress((void**)&pdotm,  d_dotm);
    cudaGetSymbolAddress((void**)&px1,    d_x1);
    cudaGetSymbolAddress((void**)&px2,    d_x2);
    cudaGetSymbolAddress((void**)&px3,    d_x3);
    cudaGetSymbolAddress((void**)&pg,     d_g);
    cudaGetSymbolAddress((void**)&pbA,    d_bA);
    cudaGetSymbolAddress((void**)&pPhiTb, d_PhiTb);

    dim3 tb16(16, 16);
    k_phitphi64<<<dim3(18, 18), tb16>>>(Phi);                       // + gamma init
    k_setupF<<<dim3(35, 8, 2), tb16>>>(Phix, Phi, Qinit, pPhiTb, px);

    for (int p = 0; p < 3; p++) {
        if (p == 0)
            k_gemmP<<<dim3(18, 8), tb16>>>(px, pz, alphas, p, 0);
        else
            k_zstep<<<BB, 256>>>(px, pz, alphas, p);
        grad_r_chain(pz, c1, c2, c3, c4, soft, px1, px2, px3, pg, pbA,
                     pz, px, pdotm, pgphi, alphas, betas, p, 0,
                     (p == 2) ? out : nullptr);
        if (p < 2) {
            k_gemmP<<<dim3(18, 8), tb16>>>(px, pdotm, alphas, p, 1);
            grad_r_chain(px, c1, c2, c3, c4, soft, px1, px2, px3, pg, pbA,
                         pz, px, pdotm, pgphi, alphas, betas, p, 1, nullptr);
            k_rownorm<<<BB, 256>>>(pgphi);
            k_gamma<<<1, 256>>>(soft);
        }
    }
}